// round 11
// baseline (speedup 1.0000x reference)
#include <cuda_runtime.h>
#include <cstdint>

#define T_DIM 256
#define D_DIM 44
#define H_DIM 8
#define NPATHS 8192
#define NGROUPS 1024
#define RING 8

// scratch
__device__ float g_hlast[NPATHS * H_DIM];
__device__ int   g_order[NPATHS];

__device__ __forceinline__ float fast_rcp(float x) {
    float r; asm("rcp.approx.f32 %0, %1;" : "=f"(r) : "f"(x)); return r;
}
__device__ __forceinline__ float fast_tanh(float x) {
    float r; asm("tanh.approx.f32 %0, %1;" : "=f"(r) : "f"(x)); return r;
}

typedef unsigned long long ull;
union F2U { ull u; float2 f; };

__device__ __forceinline__ ull pack2(float a, float b) {
    F2U t; t.f.x = a; t.f.y = b; return t.u;
}
__device__ __forceinline__ void ffma2(ull& d, ull a, ull b) {
    asm("fma.rn.f32x2 %0, %1, %2, %0;" : "+l"(d) : "l"(a), "l"(b));
}
__device__ __forceinline__ ull fma2v(ull a, ull b, ull c) {
    ull r; asm("fma.rn.f32x2 %0, %1, %2, %3;" : "=l"(r) : "l"(a), "l"(b), "l"(c)); return r;
}
__device__ __forceinline__ ull mul2(ull a, ull b) {
    ull r; asm("mul.rn.f32x2 %0, %1, %2;" : "=l"(r) : "l"(a), "l"(b)); return r;
}
__device__ __forceinline__ ull add2(ull a, ull b) {
    ull r; asm("add.rn.f32x2 %0, %1, %2;" : "=l"(r) : "l"(a), "l"(b)); return r;
}
__device__ __forceinline__ ull tanh_2(ull v) {
    F2U t; t.u = v; t.f.x = fast_tanh(t.f.x); t.f.y = fast_tanh(t.f.y); return t.u;
}

__device__ __forceinline__ unsigned int smem_u32(const void* p) {
    return (unsigned int)__cvta_generic_to_shared(p);
}
__device__ __forceinline__ void cp16_pred(unsigned int dst, const void* src, bool pred) {
    asm volatile(
        "{ .reg .pred q; setp.ne.u32 q, %2, 0;"
        " @q cp.async.ca.shared.global [%0], [%1], 16; }"
        :: "r"(dst), "l"(src), "r"((int)pred));
}
#define CP_COMMIT() asm volatile("cp.async.commit_group;" ::: "memory")
#define CP_WAIT2()  asm volatile("cp.async.wait_group 2;" ::: "memory")
#define CP_WAIT4()  asm volatile("cp.async.wait_group 4;" ::: "memory")

// ─────────────────────────────────────────────────────────────────────────────
// Counting sort by last_idx DESCENDING (parallel scan, int4-vectorized).
// ─────────────────────────────────────────────────────────────────────────────
__global__ void __launch_bounds__(1024)
sort_kernel(const int* __restrict__ last_idx)
{
    __shared__ int cnt[256];
    __shared__ int soff[256];
    __shared__ int wsum[8];
    __shared__ int wpre[8];
    const int tid = threadIdx.x;

    if (tid < 256) cnt[tid] = 0;
    __syncthreads();
    const int4* li4 = (const int4*)last_idx;
    #pragma unroll
    for (int i = tid; i < NPATHS / 4; i += 1024) {
        int4 v = li4[i];
        atomicAdd(&cnt[v.x], 1);
        atomicAdd(&cnt[v.y], 1);
        atomicAdd(&cnt[v.z], 1);
        atomicAdd(&cnt[v.w], 1);
    }
    __syncthreads();

    int v = 0;
    if (tid < 256) {
        const int r = tid;
        v = cnt[255 - r];
        #pragma unroll
        for (int d = 1; d < 32; d <<= 1) {
            int n = __shfl_up_sync(0xffffffffu, v, d);
            if ((r & 31) >= d) v += n;
        }
        if ((r & 31) == 31) wsum[r >> 5] = v;
    }
    __syncthreads();
    if (tid == 0) {
        int run = 0;
        #pragma unroll
        for (int w = 0; w < 8; w++) { wpre[w] = run; run += wsum[w]; }
    }
    __syncthreads();
    if (tid < 256) {
        const int r = tid;
        soff[255 - r] = v - cnt[255 - r] + wpre[r >> 5];
    }
    __syncthreads();
    if (tid < 256) cnt[tid] = 0;
    __syncthreads();

    #pragma unroll
    for (int i = tid; i < NPATHS / 4; i += 1024) {
        int4 L = li4[i];
        const int base = i * 4;
        g_order[soff[L.x] + atomicAdd(&cnt[L.x], 1)] = base + 0;
        g_order[soff[L.y] + atomicAdd(&cnt[L.y], 1)] = base + 1;
        g_order[soff[L.z] + atomicAdd(&cnt[L.z], 1)] = base + 2;
        g_order[soff[L.w] + atomicAdd(&cnt[L.w], 1)] = base + 3;
    }
}

// ─────────────────────────────────────────────────────────────────────────────
// LSTM: 1 warp/block, two length-matched paths packed {A,B}, MUFU tanh gates,
// 2-step unrolled loop: ONE cp.async wait per two steps, 8-deep x ring.
// ─────────────────────────────────────────────────────────────────────────────
__global__ void __launch_bounds__(32, 20)
lstm_kernel(const float* __restrict__ x,
            const float* __restrict__ W_ih,
            const float* __restrict__ W_hh,
            const float* __restrict__ b_ih,
            const float* __restrict__ b_hh,
            const int* __restrict__ last_idx)
{
    __shared__ float4 sx[RING][2][11];        // x ring: [stage][side][11 float4]
    __shared__ __align__(16) ull shh[8];      // h packed {hA[j], hB[j]}

    const int lane = threadIdx.x;
    const int pA = g_order[2 * blockIdx.x];
    const int pB = g_order[2 * blockIdx.x + 1];

    // activation mapping: sigmoid(v) = 0.5 + 0.5*tanh(0.5*v); tanh(v) = tanh(v)
    const bool isg = (lane >= 16) && (lane < 24);
    const float m_s  = isg ? 1.0f : 0.5f;     // folded into weights/bias
    const float al_s = isg ? 0.0f : 0.5f;
    const float be_s = isg ? 1.0f : 0.5f;
    const ull al2 = pack2(al_s, al_s);
    const ull be2 = pack2(be_s, be_s);

    // packed, PRE-SCALED W_ih row for this lane's gate (REGISTERS)
    ull wihP[22];
    {
        const float2* wr = (const float2*)(W_ih + lane * 44);
        #pragma unroll
        for (int k2 = 0; k2 < 22; k2++) {
            float2 v = wr[k2];
            wihP[k2] = pack2(v.x * m_s, v.y * m_s);
        }
    }
    // W_hh row, dup-packed and pre-scaled
    ull whh2[8];
    {
        const float4* wr = (const float4*)(W_hh + lane * 8);
        float4 v0 = wr[0], v1 = wr[1];
        whh2[0]=pack2(v0.x*m_s,v0.x*m_s); whh2[1]=pack2(v0.y*m_s,v0.y*m_s);
        whh2[2]=pack2(v0.z*m_s,v0.z*m_s); whh2[3]=pack2(v0.w*m_s,v0.w*m_s);
        whh2[4]=pack2(v1.x*m_s,v1.x*m_s); whh2[5]=pack2(v1.y*m_s,v1.y*m_s);
        whh2[6]=pack2(v1.z*m_s,v1.z*m_s); whh2[7]=pack2(v1.w*m_s,v1.w*m_s);
    }
    const float bias = (b_ih[lane] + b_hh[lane]) * m_s;
    const ull biasPk = pack2(bias, 0.0f);

    const int lastA = last_idx[pA];
    const int lastB = last_idx[pB];
    const int tmax  = max(lastA, lastB);
    const int jl    = lane & 7;

    const float4* xrA = (const float4*)(x + (size_t)pA * T_DIM * D_DIM);
    const float4* xrB = (const float4*)(x + (size_t)pB * T_DIM * D_DIM);

    // loaders: lanes 0-10 -> side A, lanes 16-26 -> side B
    const int  side   = lane >> 4;
    const int  slot   = lane & 15;
    const bool ldr    = slot < 11;
    const float4* myx = side ? xrB : xrA;
    const int  mylast = side ? lastB : lastA;
    const unsigned int sbase  = smem_u32(&sx[0][0][0]);
    const unsigned int mydst0 = (unsigned int)((side * 11 + slot) * 16);

    if (lane < 8) shh[lane] = 0ull;

    // prologue: prefetch stages 0..5 (one group per stage)
    #pragma unroll
    for (int p = 0; p < 6; p++) {
        cp16_pred(sbase + (unsigned int)(p * 352) + mydst0,
                  myx + (size_t)p * 11 + slot,
                  ldr && (p <= mylast));
        CP_COMMIT();
    }

    ull c2 = 0ull;
    float* outA = g_hlast + pA * H_DIM + lane;        // valid when lane < 8
    float* outB = g_hlast + pB * H_DIM + lane;

    // initial xd(0): stages 0,1 complete after wait_group 4
    ull xd2;
    CP_WAIT4();
    __syncwarp();
    {
        const ulonglong2* xsA = (const ulonglong2*)&sx[0][0][0];
        const ulonglong2* xsB = (const ulonglong2*)&sx[0][1][0];
        ull a0A = biasPk, a1A = 0ull, a0B = biasPk, a1B = 0ull;
        #pragma unroll
        for (int k = 0; k < 11; k++) {
            ulonglong2 xvA = xsA[k];
            ulonglong2 xvB = xsB[k];
            ffma2(a0A, wihP[2*k],   xvA.x);
            ffma2(a1A, wihP[2*k+1], xvA.y);
            ffma2(a0B, wihP[2*k],   xvB.x);
            ffma2(a1B, wihP[2*k+1], xvB.y);
        }
        F2U sA; sA.u = add2(a0A, a1A);
        F2U sB; sB.u = add2(a0B, a1B);
        xd2 = pack2(sA.f.x + sA.f.y, sB.f.x + sB.f.y);
    }

    for (int t = 0; t <= tmax; t += 2) {
        // at top: committed stages 0..t+5; wait -> 0..t+3 complete
        CP_WAIT2();
        __syncwarp();   // x stages visible + shh(t-1) ordered

        // ════ step t ════
        {
            const ulonglong2* hp = (const ulonglong2*)shh;
            const ulonglong2 h01 = hp[0];
            const ulonglong2 h23 = hp[1];
            const ulonglong2 h45 = hp[2];
            const ulonglong2 h67 = hp[3];

            // independent: dot(t+1)
            const int stg1 = (t + 1) & (RING - 1);
            const ulonglong2* xsA = (const ulonglong2*)&sx[stg1][0][0];
            const ulonglong2* xsB = (const ulonglong2*)&sx[stg1][1][0];
            ull a0A = biasPk, a1A = 0ull, a0B = biasPk, a1B = 0ull;
            #pragma unroll
            for (int k = 0; k < 11; k++) {
                ulonglong2 xvA = xsA[k];
                ulonglong2 xvB = xsB[k];
                ffma2(a0A, wihP[2*k],   xvA.x);
                ffma2(a1A, wihP[2*k+1], xvA.y);
                ffma2(a0B, wihP[2*k],   xvB.x);
                ffma2(a1B, wihP[2*k+1], xvB.y);
            }

            // prefetch stage t+6
            const int tp = t + 6;
            cp16_pred(sbase + (unsigned int)((tp & (RING - 1)) * 352) + mydst0,
                      myx + (size_t)tp * 11 + slot,
                      ldr && (tp <= mylast));
            CP_COMMIT();

            // chain(t)
            ull acc2 = xd2;
            ffma2(acc2, whh2[0], h01.x);
            ffma2(acc2, whh2[1], h01.y);
            ffma2(acc2, whh2[2], h23.x);
            ffma2(acc2, whh2[3], h23.y);
            ffma2(acc2, whh2[4], h45.x);
            ffma2(acc2, whh2[5], h45.y);
            ffma2(acc2, whh2[6], h67.x);
            ffma2(acc2, whh2[7], h67.y);

            const ull a2 = fma2v(be2, tanh_2(acc2), al2);

            const ull iv2 = __shfl_sync(0xffffffffu, a2, jl);
            const ull fv2 = __shfl_sync(0xffffffffu, a2, jl + 8);
            const ull gv2 = __shfl_sync(0xffffffffu, a2, jl + 16);
            const ull ov2 = __shfl_sync(0xffffffffu, a2, jl + 24);

            c2 = fma2v(fv2, c2, mul2(iv2, gv2));
            const ull hl2 = mul2(ov2, tanh_2(c2));

            if (lane < 8) {
                shh[lane] = hl2;
                F2U h; h.u = hl2;
                if (t == lastA) *outA = h.f.x;
                if (t == lastB) *outB = h.f.y;
            }

            // collapse dot(t+1) -> xd for step t+1
            F2U sA; sA.u = add2(a0A, a1A);
            F2U sB; sB.u = add2(a0B, a1B);
            xd2 = pack2(sA.f.x + sA.f.y, sB.f.x + sB.f.y);
        }

        __syncwarp();   // shh(t) visible

        // ════ step t+1 ════
        {
            const ulonglong2* hp = (const ulonglong2*)shh;
            const ulonglong2 h01 = hp[0];
            const ulonglong2 h23 = hp[1];
            const ulonglong2 h45 = hp[2];
            const ulonglong2 h67 = hp[3];

            // independent: dot(t+2) (stage complete since top wait)
            const int stg2 = (t + 2) & (RING - 1);
            const ulonglong2* xsA = (const ulonglong2*)&sx[stg2][0][0];
            const ulonglong2* xsB = (const ulonglong2*)&sx[stg2][1][0];
            ull a0A = biasPk, a1A = 0ull, a0B = biasPk, a1B = 0ull;
            #pragma unroll
            for (int k = 0; k < 11; k++) {
                ulonglong2 xvA = xsA[k];
                ulonglong2 xvB = xsB[k];
                ffma2(a0A, wihP[2*k],   xvA.x);
                ffma2(a1A, wihP[2*k+1], xvA.y);
                ffma2(a0B, wihP[2*k],   xvB.x);
                ffma2(a1B, wihP[2*k+1], xvB.y);
            }

            // prefetch stage t+7
            const int tp = t + 7;
            cp16_pred(sbase + (unsigned int)((tp & (RING - 1)) * 352) + mydst0,
                      myx + (size_t)tp * 11 + slot,
                      ldr && (tp <= mylast));
            CP_COMMIT();

            // chain(t+1)
            ull acc2 = xd2;
            ffma2(acc2, whh2[0], h01.x);
            ffma2(acc2, whh2[1], h01.y);
            ffma2(acc2, whh2[2], h23.x);
            ffma2(acc2, whh2[3], h23.y);
            ffma2(acc2, whh2[4], h45.x);
            ffma2(acc2, whh2[5], h45.y);
            ffma2(acc2, whh2[6], h67.x);
            ffma2(acc2, whh2[7], h67.y);

            const ull a2 = fma2v(be2, tanh_2(acc2), al2);

            const ull iv2 = __shfl_sync(0xffffffffu, a2, jl);
            const ull fv2 = __shfl_sync(0xffffffffu, a2, jl + 8);
            const ull gv2 = __shfl_sync(0xffffffffu, a2, jl + 16);
            const ull ov2 = __shfl_sync(0xffffffffu, a2, jl + 24);

            c2 = fma2v(fv2, c2, mul2(iv2, gv2));
            const ull hl2 = mul2(ov2, tanh_2(c2));

            if (lane < 8) {
                shh[lane] = hl2;
                F2U h; h.u = hl2;
                if (t + 1 == lastA) *outA = h.f.x;
                if (t + 1 == lastB) *outB = h.f.y;
            }

            // collapse dot(t+2) -> xd carry
            F2U sA; sA.u = add2(a0A, a1A);
            F2U sB; sB.u = add2(a0B, a1B);
            xd2 = pack2(sA.f.x + sA.f.y, sB.f.x + sB.f.y);
        }
    }
}

// ─────────────────────────────────────────────────────────────────────────────
// Finalize: per-path fc dot -> smem; counts + block scan -> segment sums;
// shfl softmax. One 1024-thread block.
// ─────────────────────────────────────────────────────────────────────────────
__global__ void __launch_bounds__(NGROUPS)
finalize_kernel(const int* __restrict__ group_ids,
                const float* __restrict__ fc_W,
                const float* __restrict__ fc_b,
                float* __restrict__ out)
{
    __shared__ float sdot[NPATHS];
    __shared__ int   scnt[NGROUPS];
    __shared__ int   sstart[NGROUPS];
    __shared__ int   wsum[32];
    __shared__ float warpred[32];
    __shared__ float bc;

    const int tid = threadIdx.x;
    const int wid = tid >> 5;
    const int lid = tid & 31;

    float w[8];
    #pragma unroll
    for (int j = 0; j < 8; j++) w[j] = fc_W[j];

    scnt[tid] = 0;
    __syncthreads();

    #pragma unroll
    for (int r = 0; r < NPATHS / NGROUPS; r++) {
        const int i = tid + r * NGROUPS;
        const float4* hp = (const float4*)(g_hlast + i * H_DIM);
        float4 h0 = hp[0], h1 = hp[1];
        float s = h0.x * w[0];
        s = fmaf(h0.y, w[1], s);
        s = fmaf(h0.z, w[2], s);
        s = fmaf(h0.w, w[3], s);
        s = fmaf(h1.x, w[4], s);
        s = fmaf(h1.y, w[5], s);
        s = fmaf(h1.z, w[6], s);
        s = fmaf(h1.w, w[7], s);
        sdot[i] = s;
        atomicAdd(&scnt[group_ids[i]], 1);
    }
    __syncthreads();

    const int myc = scnt[tid];
    int inc = myc;
    #pragma unroll
    for (int d = 1; d < 32; d <<= 1) {
        int n = __shfl_up_sync(0xffffffffu, inc, d);
        if (lid >= d) inc += n;
    }
    if (lid == 31) wsum[wid] = inc;
    __syncthreads();
    if (wid == 0) {
        int v = wsum[lid];
        int iv = v;
        #pragma unroll
        for (int d = 1; d < 32; d <<= 1) {
            int n = __shfl_up_sync(0xffffffffu, iv, d);
            if (lid >= d) iv += n;
        }
        wsum[lid] = iv - v;
    }
    __syncthreads();
    sstart[tid] = inc - myc + wsum[wid];
    __syncthreads();

    float logit = fc_b[0];
    {
        const int s = sstart[tid];
        const int e = s + myc;
        for (int i = s; i < e; i++) logit += sdot[i];
    }

    float m = logit;
    #pragma unroll
    for (int off = 16; off > 0; off >>= 1) m = fmaxf(m, __shfl_xor_sync(0xffffffffu, m, off));
    if (lid == 0) warpred[wid] = m;
    __syncthreads();
    if (wid == 0) {
        float v = warpred[lid];
        #pragma unroll
        for (int off = 16; off > 0; off >>= 1) v = fmaxf(v, __shfl_xor_sync(0xffffffffu, v, off));
        if (lid == 0) bc = v;
    }
    __syncthreads();
    const float mx = bc;

    const float e = __expf(logit - mx);

    float s = e;
    #pragma unroll
    for (int off = 16; off > 0; off >>= 1) s += __shfl_xor_sync(0xffffffffu, s, off);
    __syncthreads();
    if (lid == 0) warpred[wid] = s;
    __syncthreads();
    if (wid == 0) {
        float v = warpred[lid];
        #pragma unroll
        for (int off = 16; off > 0; off >>= 1) v += __shfl_xor_sync(0xffffffffu, v, off);
        if (lid == 0) bc = v;
    }
    __syncthreads();

    out[tid] = e * fast_rcp(bc);
}

extern "C" void kernel_launch(void* const* d_in, const int* in_sizes, int n_in,
                              void* d_out, int out_size)
{
    const float* x      = (const float*)d_in[0];
    const float* W_ih   = (const float*)d_in[1];
    const float* W_hh   = (const float*)d_in[2];
    const float* b_ih   = (const float*)d_in[3];
    const float* b_hh   = (const float*)d_in[4];
    const float* fc_W   = (const float*)d_in[5];
    const float* fc_b   = (const float*)d_in[6];
    const int*   last_i = (const int*)d_in[7];
    const int*   gids   = (const int*)d_in[8];
    float*       out    = (float*)d_out;

    sort_kernel<<<1, 1024>>>(last_i);
    lstm_kernel<<<NPATHS / 2, 32>>>(x, W_ih, W_hh, b_ih, b_hh, last_i);
    finalize_kernel<<<1, NGROUPS>>>(gids, fc_W, fc_b, out);
}

// round 12
// speedup vs baseline: 1.0663x; 1.0663x over previous
#include <cuda_runtime.h>
#include <cstdint>

#define T_DIM 256
#define D_DIM 44
#define H_DIM 8
#define NPATHS 8192
#define NGROUPS 1024
#define RING 4

// scratch
__device__ float g_hlast[NPATHS * H_DIM];
__device__ int   g_order[NPATHS];

__device__ __forceinline__ float fast_rcp(float x) {
    float r; asm("rcp.approx.f32 %0, %1;" : "=f"(r) : "f"(x)); return r;
}
__device__ __forceinline__ float fast_tanh(float x) {
    float r; asm("tanh.approx.f32 %0, %1;" : "=f"(r) : "f"(x)); return r;
}

typedef unsigned long long ull;
union F2U { ull u; float2 f; };

__device__ __forceinline__ ull pack2(float a, float b) {
    F2U t; t.f.x = a; t.f.y = b; return t.u;
}
__device__ __forceinline__ void ffma2(ull& d, ull a, ull b) {
    asm("fma.rn.f32x2 %0, %1, %2, %0;" : "+l"(d) : "l"(a), "l"(b));
}
__device__ __forceinline__ ull fma2v(ull a, ull b, ull c) {
    ull r; asm("fma.rn.f32x2 %0, %1, %2, %3;" : "=l"(r) : "l"(a), "l"(b), "l"(c)); return r;
}
__device__ __forceinline__ ull mul2(ull a, ull b) {
    ull r; asm("mul.rn.f32x2 %0, %1, %2;" : "=l"(r) : "l"(a), "l"(b)); return r;
}
__device__ __forceinline__ ull add2(ull a, ull b) {
    ull r; asm("add.rn.f32x2 %0, %1, %2;" : "=l"(r) : "l"(a), "l"(b)); return r;
}
__device__ __forceinline__ ull tanh_2(ull v) {
    F2U t; t.u = v; t.f.x = fast_tanh(t.f.x); t.f.y = fast_tanh(t.f.y); return t.u;
}

__device__ __forceinline__ unsigned int smem_u32(const void* p) {
    return (unsigned int)__cvta_generic_to_shared(p);
}
__device__ __forceinline__ void cp16_pred(unsigned int dst, const void* src, bool pred) {
    asm volatile(
        "{ .reg .pred q; setp.ne.u32 q, %2, 0;"
        " @q cp.async.ca.shared.global [%0], [%1], 16; }"
        :: "r"(dst), "l"(src), "r"((int)pred));
}
#define CP_COMMIT() asm volatile("cp.async.commit_group;" ::: "memory")
#define CP_WAIT2()  asm volatile("cp.async.wait_group 2;" ::: "memory")

// ─────────────────────────────────────────────────────────────────────────────
// Counting sort by last_idx DESCENDING (parallel scan, int4-vectorized).
// ─────────────────────────────────────────────────────────────────────────────
__global__ void __launch_bounds__(1024)
sort_kernel(const int* __restrict__ last_idx)
{
    __shared__ int cnt[256];
    __shared__ int soff[256];
    __shared__ int wsum[8];
    __shared__ int wpre[8];
    const int tid = threadIdx.x;

    if (tid < 256) cnt[tid] = 0;
    __syncthreads();
    const int4* li4 = (const int4*)last_idx;
    #pragma unroll
    for (int i = tid; i < NPATHS / 4; i += 1024) {
        int4 v = li4[i];
        atomicAdd(&cnt[v.x], 1);
        atomicAdd(&cnt[v.y], 1);
        atomicAdd(&cnt[v.z], 1);
        atomicAdd(&cnt[v.w], 1);
    }
    __syncthreads();

    int v = 0;
    if (tid < 256) {
        const int r = tid;
        v = cnt[255 - r];
        #pragma unroll
        for (int d = 1; d < 32; d <<= 1) {
            int n = __shfl_up_sync(0xffffffffu, v, d);
            if ((r & 31) >= d) v += n;
        }
        if ((r & 31) == 31) wsum[r >> 5] = v;
    }
    __syncthreads();
    if (tid == 0) {
        int run = 0;
        #pragma unroll
        for (int w = 0; w < 8; w++) { wpre[w] = run; run += wsum[w]; }
    }
    __syncthreads();
    if (tid < 256) {
        const int r = tid;
        soff[255 - r] = v - cnt[255 - r] + wpre[r >> 5];
    }
    __syncthreads();
    if (tid < 256) cnt[tid] = 0;
    __syncthreads();

    #pragma unroll
    for (int i = tid; i < NPATHS / 4; i += 1024) {
        int4 L = li4[i];
        const int base = i * 4;
        g_order[soff[L.x] + atomicAdd(&cnt[L.x], 1)] = base + 0;
        g_order[soff[L.y] + atomicAdd(&cnt[L.y], 1)] = base + 1;
        g_order[soff[L.z] + atomicAdd(&cnt[L.z], 1)] = base + 2;
        g_order[soff[L.w] + atomicAdd(&cnt[L.w], 1)] = base + 3;
    }
}

// ─────────────────────────────────────────────────────────────────────────────
// LSTM: 1 warp/block, two length-matched paths. Packed f32x2 dot (reg-lean for
// weights), SCALAR whh chain + activation epilogue (pipe-neutral, −12 regs),
// MUFU tanh, smem h handoff. 20 blocks/SM.
// ─────────────────────────────────────────────────────────────────────────────
__global__ void __launch_bounds__(32, 20)
lstm_kernel(const float* __restrict__ x,
            const float* __restrict__ W_ih,
            const float* __restrict__ W_hh,
            const float* __restrict__ b_ih,
            const float* __restrict__ b_hh,
            const int* __restrict__ last_idx)
{
    __shared__ float4 sx[RING][2][11];        // x ring: [stage][side][11 float4]
    __shared__ __align__(16) ull shh[8];      // h packed {hA[j], hB[j]}

    const int lane = threadIdx.x;
    const int pA = g_order[2 * blockIdx.x];
    const int pB = g_order[2 * blockIdx.x + 1];

    // activation: sigmoid(v) = 0.5 + 0.5*tanh(0.5*v); tanh(v) = tanh(v)
    const bool isg = (lane >= 16) && (lane < 24);
    const float m_s  = isg ? 1.0f : 0.5f;     // folded into weights/bias
    const float al_s = isg ? 0.0f : 0.5f;
    const float be_s = isg ? 1.0f : 0.5f;

    // packed, PRE-SCALED W_ih row for this lane's gate (REGISTERS)
    ull wihP[22];
    {
        const float2* wr = (const float2*)(W_ih + lane * 44);
        #pragma unroll
        for (int k2 = 0; k2 < 22; k2++) {
            float2 v = wr[k2];
            wihP[k2] = pack2(v.x * m_s, v.y * m_s);
        }
    }
    // scalar pre-scaled W_hh row
    float whh[8];
    {
        const float4* wr = (const float4*)(W_hh + lane * 8);
        float4 v0 = wr[0], v1 = wr[1];
        whh[0]=v0.x*m_s; whh[1]=v0.y*m_s; whh[2]=v0.z*m_s; whh[3]=v0.w*m_s;
        whh[4]=v1.x*m_s; whh[5]=v1.y*m_s; whh[6]=v1.z*m_s; whh[7]=v1.w*m_s;
    }
    const float bias = (b_ih[lane] + b_hh[lane]) * m_s;
    const ull biasPk = pack2(bias, 0.0f);

    const int lastA = last_idx[pA];
    const int lastB = last_idx[pB];
    const int tmax  = max(lastA, lastB);
    const int jl    = lane & 7;

    const float4* xrA = (const float4*)(x + (size_t)pA * T_DIM * D_DIM);
    const float4* xrB = (const float4*)(x + (size_t)pB * T_DIM * D_DIM);

    // loaders: lanes 0-10 -> side A, lanes 16-26 -> side B
    const int  side   = lane >> 4;
    const int  slot   = lane & 15;
    const bool ldr    = slot < 11;
    const float4* myx = side ? xrB : xrA;
    const int  mylast = side ? lastB : lastA;
    const unsigned int sbase  = smem_u32(&sx[0][0][0]);
    const unsigned int mydst0 = (unsigned int)((side * 11 + slot) * 16);

    if (lane < 8) shh[lane] = 0ull;

    // prologue: prefetch stages 0..3
    #pragma unroll
    for (int p = 0; p < RING; p++) {
        cp16_pred(sbase + (unsigned int)(p * 352) + mydst0,
                  myx + (size_t)p * 11 + slot,
                  ldr && (p <= mylast));
        CP_COMMIT();
    }

    ull c2 = 0ull;
    float* outA = g_hlast + pA * H_DIM + lane;        // valid when lane < 8
    float* outB = g_hlast + pB * H_DIM + lane;

    // initial xd(0)
    float xdA, xdB;
    CP_WAIT2();
    __syncwarp();
    {
        const ulonglong2* xsA = (const ulonglong2*)&sx[0][0][0];
        const ulonglong2* xsB = (const ulonglong2*)&sx[0][1][0];
        ull a0A = biasPk, a1A = 0ull, a0B = biasPk, a1B = 0ull;
        #pragma unroll
        for (int k = 0; k < 11; k++) {
            ulonglong2 xvA = xsA[k];
            ulonglong2 xvB = xsB[k];
            ffma2(a0A, wihP[2*k],   xvA.x);
            ffma2(a1A, wihP[2*k+1], xvA.y);
            ffma2(a0B, wihP[2*k],   xvB.x);
            ffma2(a1B, wihP[2*k+1], xvB.y);
        }
        F2U sA; sA.u = add2(a0A, a1A);
        F2U sB; sB.u = add2(a0B, a1B);
        xdA = sA.f.x + sA.f.y;
        xdB = sB.f.x + sB.f.y;
    }

    for (int t = 0; t <= tmax; t++) {
        CP_WAIT2();
        __syncwarp();   // x(t+1) visible warp-wide; also orders shh STS(t-1) -> LDS

        // load packed h(t-1): 4 warp-uniform LDS.128
        const ulonglong2* hp = (const ulonglong2*)shh;
        const ulonglong2 h01 = hp[0];
        const ulonglong2 h23 = hp[1];
        const ulonglong2 h45 = hp[2];
        const ulonglong2 h67 = hp[3];

        // ── independent: dot(t+1) for both paths ──
        const int stg1 = (t + 1) & (RING - 1);
        const ulonglong2* xsA = (const ulonglong2*)&sx[stg1][0][0];
        const ulonglong2* xsB = (const ulonglong2*)&sx[stg1][1][0];
        ull a0A = biasPk, a1A = 0ull, a0B = biasPk, a1B = 0ull;
        #pragma unroll
        for (int k = 0; k < 11; k++) {
            ulonglong2 xvA = xsA[k];
            ulonglong2 xvB = xsB[k];
            ffma2(a0A, wihP[2*k],   xvA.x);
            ffma2(a1A, wihP[2*k+1], xvA.y);
            ffma2(a0B, wihP[2*k],   xvB.x);
            ffma2(a1B, wihP[2*k+1], xvB.y);
        }

        // prefetch stage t+4
        const int tp = t + RING;
        cp16_pred(sbase + (unsigned int)((tp & (RING - 1)) * 352) + mydst0,
                  myx + (size_t)tp * 11 + slot,
                  ldr && (tp <= mylast));
        CP_COMMIT();

        // ── chain(t): scalar whh dots per path (unpack = reg aliasing, free) ──
        F2U u01, u23, u45, u67;
        u01.u = h01.x;  // wait, h01 is ulonglong2: .x = shh[0] = {hA0,hB0}
        F2U w0; w0.u = h01.x;
        F2U w1; w1.u = h01.y;
        F2U w2; w2.u = h23.x;
        F2U w3; w3.u = h23.y;
        F2U w4; w4.u = h45.x;
        F2U w5; w5.u = h45.y;
        F2U w6; w6.u = h67.x;
        F2U w7; w7.u = h67.y;

        float accA = xdA;
        accA = fmaf(whh[0], w0.f.x, accA);
        accA = fmaf(whh[1], w1.f.x, accA);
        accA = fmaf(whh[2], w2.f.x, accA);
        accA = fmaf(whh[3], w3.f.x, accA);
        accA = fmaf(whh[4], w4.f.x, accA);
        accA = fmaf(whh[5], w5.f.x, accA);
        accA = fmaf(whh[6], w6.f.x, accA);
        accA = fmaf(whh[7], w7.f.x, accA);

        float accB = xdB;
        accB = fmaf(whh[0], w0.f.y, accB);
        accB = fmaf(whh[1], w1.f.y, accB);
        accB = fmaf(whh[2], w2.f.y, accB);
        accB = fmaf(whh[3], w3.f.y, accB);
        accB = fmaf(whh[4], w4.f.y, accB);
        accB = fmaf(whh[5], w5.f.y, accB);
        accB = fmaf(whh[6], w6.f.y, accB);
        accB = fmaf(whh[7], w7.f.y, accB);

        // scalar activations (scale pre-folded): a = al + be * tanh(acc)
        const float aA = fmaf(be_s, fast_tanh(accA), al_s);
        const float aB = fmaf(be_s, fast_tanh(accB), al_s);
        const ull a2 = pack2(aA, aB);

        // gather i/f/g/o (64-bit shfl)
        const ull iv2 = __shfl_sync(0xffffffffu, a2, jl);
        const ull fv2 = __shfl_sync(0xffffffffu, a2, jl + 8);
        const ull gv2 = __shfl_sync(0xffffffffu, a2, jl + 16);
        const ull ov2 = __shfl_sync(0xffffffffu, a2, jl + 24);

        // c' = f*c + i*g ; h = o * tanh(c')   (packed {A,B})
        c2 = fma2v(fv2, c2, mul2(iv2, gv2));
        const ull hl2 = mul2(ov2, tanh_2(c2));

        // publish h (lanes 0-7; hl2 there IS {hA[j], hB[j]})
        if (lane < 8) {
            shh[lane] = hl2;
            F2U h; h.u = hl2;
            if (t == lastA) *outA = h.f.x;
            if (t == lastB) *outB = h.f.y;
        }

        // collapse next xd (off the critical chain)
        {
            F2U sA; sA.u = add2(a0A, a1A);
            F2U sB; sB.u = add2(a0B, a1B);
            xdA = sA.f.x + sA.f.y;
            xdB = sB.f.x + sB.f.y;
        }
    }
}

// ─────────────────────────────────────────────────────────────────────────────
// Finalize: per-path fc dot -> smem; counts + block scan -> segment sums;
// shfl softmax. One 1024-thread block.
// ─────────────────────────────────────────────────────────────────────────────
__global__ void __launch_bounds__(NGROUPS)
finalize_kernel(const int* __restrict__ group_ids,
                const float* __restrict__ fc_W,
                const float* __restrict__ fc_b,
                float* __restrict__ out)
{
    __shared__ float sdot[NPATHS];
    __shared__ int   scnt[NGROUPS];
    __shared__ int   sstart[NGROUPS];
    __shared__ int   wsum[32];
    __shared__ float warpred[32];
    __shared__ float bc;

    const int tid = threadIdx.x;
    const int wid = tid >> 5;
    const int lid = tid & 31;

    float w[8];
    #pragma unroll
    for (int j = 0; j < 8; j++) w[j] = fc_W[j];

    scnt[tid] = 0;
    __syncthreads();

    #pragma unroll
    for (int r = 0; r < NPATHS / NGROUPS; r++) {
        const int i = tid + r * NGROUPS;
        const float4* hp = (const float4*)(g_hlast + i * H_DIM);
        float4 h0 = hp[0], h1 = hp[1];
        float s = h0.x * w[0];
        s = fmaf(h0.y, w[1], s);
        s = fmaf(h0.z, w[2], s);
        s = fmaf(h0.w, w[3], s);
        s = fmaf(h1.x, w[4], s);
        s = fmaf(h1.y, w[5], s);
        s = fmaf(h1.z, w[6], s);
        s = fmaf(h1.w, w[7], s);
        sdot[i] = s;
        atomicAdd(&scnt[group_ids[i]], 1);
    }
    __syncthreads();

    const int myc = scnt[tid];
    int inc = myc;
    #pragma unroll
    for (int d = 1; d < 32; d <<= 1) {
        int n = __shfl_up_sync(0xffffffffu, inc, d);
        if (lid >= d) inc += n;
    }
    if (lid == 31) wsum[wid] = inc;
    __syncthreads();
    if (wid == 0) {
        int v = wsum[lid];
        int iv = v;
        #pragma unroll
        for (int d = 1; d < 32; d <<= 1) {
            int n = __shfl_up_sync(0xffffffffu, iv, d);
            if (lid >= d) iv += n;
        }
        wsum[lid] = iv - v;
    }
    __syncthreads();
    sstart[tid] = inc - myc + wsum[wid];
    __syncthreads();

    float logit = fc_b[0];
    {
        const int s = sstart[tid];
        const int e = s + myc;
        for (int i = s; i < e; i++) logit += sdot[i];
    }

    float m = logit;
    #pragma unroll
    for (int off = 16; off > 0; off >>= 1) m = fmaxf(m, __shfl_xor_sync(0xffffffffu, m, off));
    if (lid == 0) warpred[wid] = m;
    __syncthreads();
    if (wid == 0) {
        float v = warpred[lid];
        #pragma unroll
        for (int off = 16; off > 0; off >>= 1) v = fmaxf(v, __shfl_xor_sync(0xffffffffu, v, off));
        if (lid == 0) bc = v;
    }
    __syncthreads();
    const float mx = bc;

    const float e = __expf(logit - mx);

    float s = e;
    #pragma unroll
    for (int off = 16; off > 0; off >>= 1) s += __shfl_xor_sync(0xffffffffu, s, off);
    __syncthreads();
    if (lid == 0) warpred[wid] = s;
    __syncthreads();
    if (wid == 0) {
        float v = warpred[lid];
        #pragma unroll
        for (int off = 16; off > 0; off >>= 1) v += __shfl_xor_sync(0xffffffffu, v, off);
        if (lid == 0) bc = v;
    }
    __syncthreads();

    out[tid] = e * fast_rcp(bc);
}

extern "C" void kernel_launch(void* const* d_in, const int* in_sizes, int n_in,
                              void* d_out, int out_size)
{
    const float* x      = (const float*)d_in[0];
    const float* W_ih   = (const float*)d_in[1];
    const float* W_hh   = (const float*)d_in[2];
    const float* b_ih   = (const float*)d_in[3];
    const float* b_hh   = (const float*)d_in[4];
    const float* fc_W   = (const float*)d_in[5];
    const float* fc_b   = (const float*)d_in[6];
    const int*   last_i = (const int*)d_in[7];
    const int*   gids   = (const int*)d_in[8];
    float*       out    = (float*)d_out;

    sort_kernel<<<1, 1024>>>(last_i);
    lstm_kernel<<<NPATHS / 2, 32>>>(x, W_ih, W_hh, b_ih, b_hh, last_i);
    finalize_kernel<<<1, NGROUPS>>>(gids, fc_W, fc_b, out);
}

// round 13
// speedup vs baseline: 1.6081x; 1.5081x over previous
#include <cuda_runtime.h>
#include <cstdint>

#define T_DIM 256
#define D_DIM 44
#define H_DIM 8
#define NPATHS 8192
#define NGROUPS 1024
#define RING 4
#define PPW 8                         // paths per warp
#define NBLK (NPATHS / PPW)           // 1024
#define SIDE_F 52                     // floats per path-side in ring (13 float4, conflict-free stride)
#define STAGE_B (PPW * SIDE_F * 4)    // bytes per ring stage

// scratch
__device__ float g_hlast[NPATHS * H_DIM];
__device__ int   g_order[NPATHS];

__device__ __forceinline__ float fast_rcp(float x) {
    float r; asm("rcp.approx.f32 %0, %1;" : "=f"(r) : "f"(x)); return r;
}
__device__ __forceinline__ float fast_tanh(float x) {
    float r; asm("tanh.approx.f32 %0, %1;" : "=f"(r) : "f"(x)); return r;
}
__device__ __forceinline__ unsigned int to_tf32(float x) {
    unsigned int r; asm("cvt.rna.tf32.f32 %0, %1;" : "=r"(r) : "f"(x)); return r;
}
__device__ __forceinline__ void mma_tf32(float& c0, float& c1, float& c2, float& c3,
                                         unsigned int a0, unsigned int a1,
                                         unsigned int a2, unsigned int a3,
                                         unsigned int b0, unsigned int b1) {
    asm("mma.sync.aligned.m16n8k8.row.col.f32.tf32.tf32.f32 "
        "{%0,%1,%2,%3}, {%4,%5,%6,%7}, {%8,%9}, {%0,%1,%2,%3};"
        : "+f"(c0), "+f"(c1), "+f"(c2), "+f"(c3)
        : "r"(a0), "r"(a1), "r"(a2), "r"(a3), "r"(b0), "r"(b1));
}

__device__ __forceinline__ unsigned int smem_u32(const void* p) {
    return (unsigned int)__cvta_generic_to_shared(p);
}
__device__ __forceinline__ void cp16_pred(unsigned int dst, const void* src, bool pred) {
    asm volatile(
        "{ .reg .pred q; setp.ne.u32 q, %2, 0;"
        " @q cp.async.ca.shared.global [%0], [%1], 16; }"
        :: "r"(dst), "l"(src), "r"((int)pred));
}
#define CP_COMMIT() asm volatile("cp.async.commit_group;" ::: "memory")
#define CP_WAIT2()  asm volatile("cp.async.wait_group 2;" ::: "memory")

// ─────────────────────────────────────────────────────────────────────────────
// Counting sort by last_idx DESCENDING (parallel scan, int4-vectorized).
// ─────────────────────────────────────────────────────────────────────────────
__global__ void __launch_bounds__(1024)
sort_kernel(const int* __restrict__ last_idx)
{
    __shared__ int cnt[256];
    __shared__ int soff[256];
    __shared__ int wsum[8];
    __shared__ int wpre[8];
    const int tid = threadIdx.x;

    if (tid < 256) cnt[tid] = 0;
    __syncthreads();
    const int4* li4 = (const int4*)last_idx;
    #pragma unroll
    for (int i = tid; i < NPATHS / 4; i += 1024) {
        int4 v = li4[i];
        atomicAdd(&cnt[v.x], 1);
        atomicAdd(&cnt[v.y], 1);
        atomicAdd(&cnt[v.z], 1);
        atomicAdd(&cnt[v.w], 1);
    }
    __syncthreads();

    int v = 0;
    if (tid < 256) {
        const int r = tid;
        v = cnt[255 - r];
        #pragma unroll
        for (int d = 1; d < 32; d <<= 1) {
            int n = __shfl_up_sync(0xffffffffu, v, d);
            if ((r & 31) >= d) v += n;
        }
        if ((r & 31) == 31) wsum[r >> 5] = v;
    }
    __syncthreads();
    if (tid == 0) {
        int run = 0;
        #pragma unroll
        for (int w = 0; w < 8; w++) { wpre[w] = run; run += wsum[w]; }
    }
    __syncthreads();
    if (tid < 256) {
        const int r = tid;
        soff[255 - r] = v - cnt[255 - r] + wpre[r >> 5];
    }
    __syncthreads();
    if (tid < 256) cnt[tid] = 0;
    __syncthreads();

    #pragma unroll
    for (int i = tid; i < NPATHS / 4; i += 1024) {
        int4 L = li4[i];
        const int base = i * 4;
        g_order[soff[L.x] + atomicAdd(&cnt[L.x], 1)] = base + 0;
        g_order[soff[L.y] + atomicAdd(&cnt[L.y], 1)] = base + 1;
        g_order[soff[L.z] + atomicAdd(&cnt[L.z], 1)] = base + 2;
        g_order[soff[L.w] + atomicAdd(&cnt[L.w], 1)] = base + 3;
    }
}

// ─────────────────────────────────────────────────────────────────────────────
// LSTM via tf32 tensor-core MMA: 1 warp per block, 8 length-matched paths.
// gates[32,8] = W_ext[32,56] @ [x_t ; pad ; h][56,8] as 2x m16n8k8 per k-chunk.
// C layout puts all 4 gates (both paths 2*tig, 2*tig+1) of hidden grp on one
// lane -> no gate shuffles. h exchanged via 64-float smem. x via cp.async ring.
// ─────────────────────────────────────────────────────────────────────────────
__global__ void __launch_bounds__(32)
lstm_kernel(const float* __restrict__ x,
            const float* __restrict__ W_ih,
            const float* __restrict__ W_hh,
            const float* __restrict__ b_ih,
            const float* __restrict__ b_hh,
            const int* __restrict__ last_idx)
{
    __shared__ float sx[RING][PPW][SIDE_F];   // x ring (floats 44..51 = zero pad)
    __shared__ float wext[32][56];            // [gate row][k] pre-scaled
    __shared__ float shh[PPW][8];             // h[path][hidden]

    const int lane = threadIdx.x;
    const int grp  = lane >> 2;   // 0..7
    const int tig  = lane & 3;    // 0..3
    const int* ord = g_order + PPW * blockIdx.x;

    // this lane's two paths (C cols 2*tig, 2*tig+1)
    const int p0 = ord[2 * tig];
    const int p1 = ord[2 * tig + 1];
    const int last0 = last_idx[p0];
    const int last1 = last_idx[p1];
    int tmax = max(last0, last1);
    tmax = max(tmax, __shfl_xor_sync(0xffffffffu, tmax, 1));
    tmax = max(tmax, __shfl_xor_sync(0xffffffffu, tmax, 2));

    // build W_ext row (this lane's gate row), activation scale folded in
    {
        const bool isg = (lane >= 16) && (lane < 24);
        const float m = isg ? 1.0f : 0.5f;
        const float* wr = W_ih + lane * 44;
        #pragma unroll 4
        for (int k = 0; k < 44; k++) wext[lane][k] = wr[k] * m;
        wext[lane][44] = 0.f; wext[lane][45] = 0.f;
        wext[lane][46] = 0.f; wext[lane][47] = 0.f;
        const float* wh = W_hh + lane * 8;
        #pragma unroll
        for (int q = 0; q < 8; q++) wext[lane][48 + q] = wh[q] * m;
    }
    // biases (scaled) for rows grp(+8/16/24)
    const float bi_i = (b_ih[grp]      + b_hh[grp])      * 0.5f;
    const float bi_f = (b_ih[grp + 8]  + b_hh[grp + 8])  * 0.5f;
    const float bi_g = (b_ih[grp + 16] + b_hh[grp + 16]);
    const float bi_o = (b_ih[grp + 24] + b_hh[grp + 24]) * 0.5f;

    // zero ring pads (floats 44..51 of each side) + h buffer
    {
        const int st = lane >> 3, sd = lane & 7;
        float4* pad = (float4*)&sx[st][sd][44];
        pad[0] = make_float4(0, 0, 0, 0);
        pad[1] = make_float4(0, 0, 0, 0);
    }
    shh[grp][tig] = 0.f;
    shh[grp][tig + 4] = 0.f;
    __syncwarp();

    // A fragments (weights), in registers, tf32
    unsigned int afr[7][2][4];
    #pragma unroll
    for (int cc = 0; cc < 7; cc++) {
        #pragma unroll
        for (int hh = 0; hh < 2; hh++) {
            const int r0 = hh * 16 + grp;
            afr[cc][hh][0] = to_tf32(wext[r0][cc * 8 + tig]);
            afr[cc][hh][1] = to_tf32(wext[r0 + 8][cc * 8 + tig]);
            afr[cc][hh][2] = to_tf32(wext[r0][cc * 8 + tig + 4]);
            afr[cc][hh][3] = to_tf32(wext[r0 + 8][cc * 8 + tig + 4]);
        }
    }

    // loader slots: 88 (path, quad) pairs over 3 rounds of 32 lanes
    const float* xsrc[3];
    int  plastS[3];
    unsigned int sdst[3];
    bool pval[3];
    #pragma unroll
    for (int s = 0; s < 3; s++) {
        const int i = lane + 32 * s;
        pval[s] = (i < 88);
        const int pi = pval[s] ? (i / 11) : 0;
        const int qi = pval[s] ? (i % 11) : 0;
        const int pp = ord[pi];
        xsrc[s]   = x + (size_t)pp * T_DIM * D_DIM + qi * 4;
        plastS[s] = last_idx[pp];
        sdst[s]   = (unsigned int)((pi * SIDE_F + qi * 4) * 4);
    }
    const unsigned int sbase = smem_u32(&sx[0][0][0]);

    // prologue: fill stages 0..3 (rows clamped so every slot holds valid data)
    #pragma unroll
    for (int p = 0; p < RING; p++) {
        #pragma unroll
        for (int s = 0; s < 3; s++) {
            const int row = min(p, plastS[s]);
            cp16_pred(sbase + (unsigned int)(p * STAGE_B) + sdst[s],
                      xsrc[s] + (size_t)row * 44, pval[s]);
        }
        CP_COMMIT();
    }

    float cc0 = 0.f, cc1 = 0.f;                 // cell state (2 paths, hidden grp)
    float* out0 = g_hlast + p0 * H_DIM + grp;
    float* out1 = g_hlast + p1 * H_DIM + grp;

    float Cc[2][4], Cn[2][4];

    // initial xdot(0) -> Cc
    CP_WAIT2();
    __syncwarp();
    {
        const float* xp = &sx[0][grp][0];
        Cc[0][0] = bi_i; Cc[0][1] = bi_i; Cc[0][2] = bi_f; Cc[0][3] = bi_f;
        Cc[1][0] = bi_g; Cc[1][1] = bi_g; Cc[1][2] = bi_o; Cc[1][3] = bi_o;
        #pragma unroll
        for (int cc = 0; cc < 6; cc++) {
            const unsigned int b0 = to_tf32(xp[cc * 8 + tig]);
            const unsigned int b1 = to_tf32(xp[cc * 8 + tig + 4]);
            mma_tf32(Cc[0][0], Cc[0][1], Cc[0][2], Cc[0][3],
                     afr[cc][0][0], afr[cc][0][1], afr[cc][0][2], afr[cc][0][3], b0, b1);
            mma_tf32(Cc[1][0], Cc[1][1], Cc[1][2], Cc[1][3],
                     afr[cc][1][0], afr[cc][1][1], afr[cc][1][2], afr[cc][1][3], b0, b1);
        }
    }

    for (int t = 0; t <= tmax; t++) {
        CP_WAIT2();
        __syncwarp();   // stage t+1 visible; shh(t-1) ordered

        // ── chain head: add W_hh · h(t-1) into Cc (k-chunk 6) ──
        {
            const unsigned int hb0 = to_tf32(shh[grp][tig]);
            const unsigned int hb1 = to_tf32(shh[grp][tig + 4]);
            mma_tf32(Cc[0][0], Cc[0][1], Cc[0][2], Cc[0][3],
                     afr[6][0][0], afr[6][0][1], afr[6][0][2], afr[6][0][3], hb0, hb1);
            mma_tf32(Cc[1][0], Cc[1][1], Cc[1][2], Cc[1][3],
                     afr[6][1][0], afr[6][1][1], afr[6][1][2], afr[6][1][3], hb0, hb1);
        }

        // ── independent: Cn = bias + W_ih · x(t+1)  (fills chain shadows) ──
        {
            const float* xp = &sx[(t + 1) & (RING - 1)][grp][0];
            Cn[0][0] = bi_i; Cn[0][1] = bi_i; Cn[0][2] = bi_f; Cn[0][3] = bi_f;
            Cn[1][0] = bi_g; Cn[1][1] = bi_g; Cn[1][2] = bi_o; Cn[1][3] = bi_o;
            #pragma unroll
            for (int cc = 0; cc < 6; cc++) {
                const unsigned int b0 = to_tf32(xp[cc * 8 + tig]);
                const unsigned int b1 = to_tf32(xp[cc * 8 + tig + 4]);
                mma_tf32(Cn[0][0], Cn[0][1], Cn[0][2], Cn[0][3],
                         afr[cc][0][0], afr[cc][0][1], afr[cc][0][2], afr[cc][0][3], b0, b1);
                mma_tf32(Cn[1][0], Cn[1][1], Cn[1][2], Cn[1][3],
                         afr[cc][1][0], afr[cc][1][1], afr[cc][1][2], afr[cc][1][3], b0, b1);
            }
        }

        // prefetch stage t+4
        {
            const int tp = t + RING;
            #pragma unroll
            for (int s = 0; s < 3; s++) {
                cp16_pred(sbase + (unsigned int)(((tp & (RING - 1)) * STAGE_B)) + sdst[s],
                          xsrc[s] + (size_t)min(tp, plastS[s]) * 44,
                          pval[s] && (tp <= plastS[s]));
            }
            CP_COMMIT();
        }

        // ── chain tail: activations + cell + h (all gates local to this lane) ──
        const float i0 = fmaf(0.5f, fast_tanh(Cc[0][0]), 0.5f);
        const float i1 = fmaf(0.5f, fast_tanh(Cc[0][1]), 0.5f);
        const float f0 = fmaf(0.5f, fast_tanh(Cc[0][2]), 0.5f);
        const float f1 = fmaf(0.5f, fast_tanh(Cc[0][3]), 0.5f);
        const float g0 = fast_tanh(Cc[1][0]);
        const float g1 = fast_tanh(Cc[1][1]);
        const float o0 = fmaf(0.5f, fast_tanh(Cc[1][2]), 0.5f);
        const float o1 = fmaf(0.5f, fast_tanh(Cc[1][3]), 0.5f);

        cc0 = fmaf(f0, cc0, i0 * g0);
        cc1 = fmaf(f1, cc1, i1 * g1);
        const float h0 = o0 * fast_tanh(cc0);
        const float h1 = o1 * fast_tanh(cc1);

        if (t == last0) *out0 = h0;
        if (t == last1) *out1 = h1;
        shh[2 * tig][grp]     = h0;
        shh[2 * tig + 1][grp] = h1;

        // Cc <- Cn
        Cc[0][0] = Cn[0][0]; Cc[0][1] = Cn[0][1]; Cc[0][2] = Cn[0][2]; Cc[0][3] = Cn[0][3];
        Cc[1][0] = Cn[1][0]; Cc[1][1] = Cn[1][1]; Cc[1][2] = Cn[1][2]; Cc[1][3] = Cn[1][3];
    }
}

// ─────────────────────────────────────────────────────────────────────────────
// Finalize: per-path fc dot -> smem; counts + block scan -> segment sums;
// shfl softmax. One 1024-thread block.
// ─────────────────────────────────────────────────────────────────────────────
__global__ void __launch_bounds__(NGROUPS)
finalize_kernel(const int* __restrict__ group_ids,
                const float* __restrict__ fc_W,
                const float* __restrict__ fc_b,
                float* __restrict__ out)
{
    __shared__ float sdot[NPATHS];
    __shared__ int   scnt[NGROUPS];
    __shared__ int   sstart[NGROUPS];
    __shared__ int   wsum[32];
    __shared__ float warpred[32];
    __shared__ float bc;

    const int tid = threadIdx.x;
    const int wid = tid >> 5;
    const int lid = tid & 31;

    float w[8];
    #pragma unroll
    for (int j = 0; j < 8; j++) w[j] = fc_W[j];

    scnt[tid] = 0;
    __syncthreads();

    #pragma unroll
    for (int r = 0; r < NPATHS / NGROUPS; r++) {
        const int i = tid + r * NGROUPS;
        const float4* hp = (const float4*)(g_hlast + i * H_DIM);
        float4 h0 = hp[0], h1 = hp[1];
        float s = h0.x * w[0];
        s = fmaf(h0.y, w[1], s);
        s = fmaf(h0.z, w[2], s);
        s = fmaf(h0.w, w[3], s);
        s = fmaf(h1.x, w[4], s);
        s = fmaf(h1.y, w[5], s);
        s = fmaf(h1.z, w[6], s);
        s = fmaf(h1.w, w[7], s);
        sdot[i] = s;
        atomicAdd(&scnt[group_ids[i]], 1);
    }
    __syncthreads();

    const int myc = scnt[tid];
    int inc = myc;
    #pragma unroll
    for (int d = 1; d < 32; d <<= 1) {
        int n = __shfl_up_sync(0xffffffffu, inc, d);
        if (lid >= d) inc += n;
    }
    if (lid == 31) wsum[wid] = inc;
    __syncthreads();
    if (wid == 0) {
        int v = wsum[lid];
        int iv = v;
        #pragma unroll
        for (int d = 1; d < 32; d <<= 1) {
            int n = __shfl_up_sync(0xffffffffu, iv, d);
            if (lid >= d) iv += n;
        }
        wsum[lid] = iv - v;
    }
    __syncthreads();
    sstart[tid] = inc - myc + wsum[wid];
    __syncthreads();

    float logit = fc_b[0];
    {
        const int s = sstart[tid];
        const int e = s + myc;
        for (int i = s; i < e; i++) logit += sdot[i];
    }

    float m = logit;
    #pragma unroll
    for (int off = 16; off > 0; off >>= 1) m = fmaxf(m, __shfl_xor_sync(0xffffffffu, m, off));
    if (lid == 0) warpred[wid] = m;
    __syncthreads();
    if (wid == 0) {
        float v = warpred[lid];
        #pragma unroll
        for (int off = 16; off > 0; off >>= 1) v = fmaxf(v, __shfl_xor_sync(0xffffffffu, v, off));
        if (lid == 0) bc = v;
    }
    __syncthreads();
    const float mx = bc;

    const float e = __expf(logit - mx);

    float s = e;
    #pragma unroll
    for (int off = 16; off > 0; off >>= 1) s += __shfl_xor_sync(0xffffffffu, s, off);
    __syncthreads();
    if (lid == 0) warpred[wid] = s;
    __syncthreads();
    if (wid == 0) {
        float v = warpred[lid];
        #pragma unroll
        for (int off = 16; off > 0; off >>= 1) v += __shfl_xor_sync(0xffffffffu, v, off);
        if (lid == 0) bc = v;
    }
    __syncthreads();

    out[tid] = e * fast_rcp(bc);
}

extern "C" void kernel_launch(void* const* d_in, const int* in_sizes, int n_in,
                              void* d_out, int out_size)
{
    const float* x      = (const float*)d_in[0];
    const float* W_ih   = (const float*)d_in[1];
    const float* W_hh   = (const float*)d_in[2];
    const float* b_ih   = (const float*)d_in[3];
    const float* b_hh   = (const float*)d_in[4];
    const float* fc_W   = (const float*)d_in[5];
    const float* fc_b   = (const float*)d_in[6];
    const int*   last_i = (const int*)d_in[7];
    const int*   gids   = (const int*)d_in[8];
    float*       out    = (float*)d_out;

    sort_kernel<<<1, 1024>>>(last_i);
    lstm_kernel<<<NBLK, 32>>>(x, W_ih, W_hh, b_ih, b_hh, last_i);
    finalize_kernel<<<1, NGROUPS>>>(gids, fc_W, fc_b, out);
}

// round 15
// speedup vs baseline: 1.6608x; 1.0328x over previous
#include <cuda_runtime.h>
#include <cstdint>

#define T_DIM 256
#define D_DIM 44
#define H_DIM 8
#define NPATHS 8192
#define NGROUPS 1024
#define RING 4
#define PPW 8                         // paths per warp
#define NBLK (NPATHS / PPW)           // 1024
#define SIDE_F 52                     // floats per path-side in ring (conflict-free stride)
#define STAGE_B (PPW * SIDE_F * 4)    // bytes per ring stage

// scratch
__device__ float g_hlast[NPATHS * H_DIM];
__device__ int   g_order[NPATHS];

__device__ __forceinline__ float fast_rcp(float x) {
    float r; asm("rcp.approx.f32 %0, %1;" : "=f"(r) : "f"(x)); return r;
}
__device__ __forceinline__ float fast_tanh(float x) {
    float r; asm("tanh.approx.f32 %0, %1;" : "=f"(r) : "f"(x)); return r;
}
__device__ __forceinline__ unsigned int to_tf32(float x) {
    unsigned int r; asm("cvt.rna.tf32.f32 %0, %1;" : "=r"(r) : "f"(x)); return r;
}
__device__ __forceinline__ void mma_tf32(float& c0, float& c1, float& c2, float& c3,
                                         unsigned int a0, unsigned int a1,
                                         unsigned int a2, unsigned int a3,
                                         unsigned int b0, unsigned int b1) {
    asm("mma.sync.aligned.m16n8k8.row.col.f32.tf32.tf32.f32 "
        "{%0,%1,%2,%3}, {%4,%5,%6,%7}, {%8,%9}, {%0,%1,%2,%3};"
        : "+f"(c0), "+f"(c1), "+f"(c2), "+f"(c3)
        : "r"(a0), "r"(a1), "r"(a2), "r"(a3), "r"(b0), "r"(b1));
}

__device__ __forceinline__ unsigned int smem_u32(const void* p) {
    return (unsigned int)__cvta_generic_to_shared(p);
}
__device__ __forceinline__ void cp16_pred(unsigned int dst, const void* src, bool pred) {
    asm volatile(
        "{ .reg .pred q; setp.ne.u32 q, %2, 0;"
        " @q cp.async.ca.shared.global [%0], [%1], 16; }"
        :: "r"(dst), "l"(src), "r"((int)pred));
}
#define CP_COMMIT() asm volatile("cp.async.commit_group;" ::: "memory")
#define CP_WAIT2()  asm volatile("cp.async.wait_group 2;" ::: "memory")

// ─────────────────────────────────────────────────────────────────────────────
// Counting sort by last_idx DESCENDING (parallel scan, int4-vectorized).
// ─────────────────────────────────────────────────────────────────────────────
__global__ void __launch_bounds__(1024)
sort_kernel(const int* __restrict__ last_idx)
{
    __shared__ int cnt[256];
    __shared__ int soff[256];
    __shared__ int wsum[8];
    __shared__ int wpre[8];
    const int tid = threadIdx.x;

    if (tid < 256) cnt[tid] = 0;
    __syncthreads();
    const int4* li4 = (const int4*)last_idx;
    #pragma unroll
    for (int i = tid; i < NPATHS / 4; i += 1024) {
        int4 v = li4[i];
        atomicAdd(&cnt[v.x], 1);
        atomicAdd(&cnt[v.y], 1);
        atomicAdd(&cnt[v.z], 1);
        atomicAdd(&cnt[v.w], 1);
    }
    __syncthreads();

    int v = 0;
    if (tid < 256) {
        const int r = tid;
        v = cnt[255 - r];
        #pragma unroll
        for (int d = 1; d < 32; d <<= 1) {
            int n = __shfl_up_sync(0xffffffffu, v, d);
            if ((r & 31) >= d) v += n;
        }
        if ((r & 31) == 31) wsum[r >> 5] = v;
    }
    __syncthreads();
    if (tid == 0) {
        int run = 0;
        #pragma unroll
        for (int w = 0; w < 8; w++) { wpre[w] = run; run += wsum[w]; }
    }
    __syncthreads();
    if (tid < 256) {
        const int r = tid;
        soff[255 - r] = v - cnt[255 - r] + wpre[r >> 5];
    }
    __syncthreads();
    if (tid < 256) cnt[tid] = 0;
    __syncthreads();

    #pragma unroll
    for (int i = tid; i < NPATHS / 4; i += 1024) {
        int4 L = li4[i];
        const int base = i * 4;
        g_order[soff[L.x] + atomicAdd(&cnt[L.x], 1)] = base + 0;
        g_order[soff[L.y] + atomicAdd(&cnt[L.y], 1)] = base + 1;
        g_order[soff[L.z] + atomicAdd(&cnt[L.z], 1)] = base + 2;
        g_order[soff[L.w] + atomicAdd(&cnt[L.w], 1)] = base + 3;
    }
}

// ─────────────────────────────────────────────────────────────────────────────
// LSTM via tf32 MMA, chain-minimized: h redistributed by 4 SHFL + selects
// (register transpose, no smem/barrier on the chain); all per-step tf32
// conversions dropped (raw fp32 bits, HW truncates). One syncwarp per step
// (x-ring visibility only).
// ─────────────────────────────────────────────────────────────────────────────
__global__ void __launch_bounds__(32)
lstm_kernel(const float* __restrict__ x,
            const float* __restrict__ W_ih,
            const float* __restrict__ W_hh,
            const float* __restrict__ b_ih,
            const float* __restrict__ b_hh,
            const int* __restrict__ last_idx)
{
    __shared__ float sx[RING][PPW][SIDE_F];   // x ring (floats 44..51 = zero pad)
    __shared__ float wext[32][56];            // [gate row][k] pre-scaled

    const int lane = threadIdx.x;
    const int grp  = lane >> 2;   // 0..7
    const int tig  = lane & 3;    // 0..3
    const int* ord = g_order + PPW * blockIdx.x;

    // this lane's two paths (C cols 2*tig, 2*tig+1)
    const int p0 = ord[2 * tig];
    const int p1 = ord[2 * tig + 1];
    const int last0 = last_idx[p0];
    const int last1 = last_idx[p1];
    int tmax = max(last0, last1);
    tmax = max(tmax, __shfl_xor_sync(0xffffffffu, tmax, 1));
    tmax = max(tmax, __shfl_xor_sync(0xffffffffu, tmax, 2));

    // build W_ext row (this lane's gate row), activation scale folded in
    {
        const bool isg = (lane >= 16) && (lane < 24);
        const float m = isg ? 1.0f : 0.5f;
        const float* wr = W_ih + lane * 44;
        #pragma unroll 4
        for (int k = 0; k < 44; k++) wext[lane][k] = wr[k] * m;
        wext[lane][44] = 0.f; wext[lane][45] = 0.f;
        wext[lane][46] = 0.f; wext[lane][47] = 0.f;
        const float* wh = W_hh + lane * 8;
        #pragma unroll
        for (int q = 0; q < 8; q++) wext[lane][48 + q] = wh[q] * m;
    }
    // biases (scaled) for rows grp(+8/16/24)
    const float bi_i = (b_ih[grp]      + b_hh[grp])      * 0.5f;
    const float bi_f = (b_ih[grp + 8]  + b_hh[grp + 8])  * 0.5f;
    const float bi_g = (b_ih[grp + 16] + b_hh[grp + 16]);
    const float bi_o = (b_ih[grp + 24] + b_hh[grp + 24]) * 0.5f;

    // zero ring pads (floats 44..51 of each side)
    {
        const int st = lane >> 3, sd = lane & 7;
        float4* pad = (float4*)&sx[st][sd][44];
        pad[0] = make_float4(0, 0, 0, 0);
        pad[1] = make_float4(0, 0, 0, 0);
    }
    __syncwarp();

    // A fragments (weights), in registers, tf32 (rounded once)
    unsigned int afr[7][2][4];
    #pragma unroll
    for (int cc = 0; cc < 7; cc++) {
        #pragma unroll
        for (int hh = 0; hh < 2; hh++) {
            const int r0 = hh * 16 + grp;
            afr[cc][hh][0] = to_tf32(wext[r0][cc * 8 + tig]);
            afr[cc][hh][1] = to_tf32(wext[r0 + 8][cc * 8 + tig]);
            afr[cc][hh][2] = to_tf32(wext[r0][cc * 8 + tig + 4]);
            afr[cc][hh][3] = to_tf32(wext[r0 + 8][cc * 8 + tig + 4]);
        }
    }

    // h shuffle sources: b0 needs h[path=grp][hid=tig] from lane tig*4+(grp>>1);
    // b1 needs hid=tig+4 from lane 16+tig*4+(grp>>1). h0/h1 chosen by grp parity.
    const int srcA = tig * 4 + (grp >> 1);
    const int srcB = srcA + 16;
    const bool oddp = (grp & 1);

    // loader slots: 88 (path, quad) pairs over 3 rounds of 32 lanes
    const float* xsrc[3];
    int  plastS[3];
    unsigned int sdst[3];
    bool pval[3];
    #pragma unroll
    for (int s = 0; s < 3; s++) {
        const int i = lane + 32 * s;
        pval[s] = (i < 88);
        const int pi = pval[s] ? (i / 11) : 0;
        const int qi = pval[s] ? (i % 11) : 0;
        const int pp = ord[pi];
        xsrc[s]   = x + (size_t)pp * T_DIM * D_DIM + qi * 4;
        plastS[s] = last_idx[pp];
        sdst[s]   = (unsigned int)((pi * SIDE_F + qi * 4) * 4);
    }
    const unsigned int sbase = smem_u32(&sx[0][0][0]);

    // prologue: fill stages 0..3 (rows clamped so every slot holds valid data)
    #pragma unroll
    for (int p = 0; p < RING; p++) {
        #pragma unroll
        for (int s = 0; s < 3; s++) {
            const int row = min(p, plastS[s]);
            cp16_pred(sbase + (unsigned int)(p * STAGE_B) + sdst[s],
                      xsrc[s] + (size_t)row * 44, pval[s]);
        }
        CP_COMMIT();
    }

    float cc0 = 0.f, cc1 = 0.f;                 // cell state (2 paths, hidden grp)
    float h0 = 0.f, h1 = 0.f;                   // hidden (2 paths, hidden grp)
    float* out0 = g_hlast + p0 * H_DIM + grp;
    float* out1 = g_hlast + p1 * H_DIM + grp;

    float Cc[2][4], Cn[2][4];

    // initial xdot(0) -> Cc (raw fp32 bits as tf32 operands)
    CP_WAIT2();
    __syncwarp();
    {
        const unsigned int* xp = (const unsigned int*)&sx[0][grp][0];
        Cc[0][0] = bi_i; Cc[0][1] = bi_i; Cc[0][2] = bi_f; Cc[0][3] = bi_f;
        Cc[1][0] = bi_g; Cc[1][1] = bi_g; Cc[1][2] = bi_o; Cc[1][3] = bi_o;
        #pragma unroll
        for (int cc = 0; cc < 6; cc++) {
            const unsigned int b0 = xp[cc * 8 + tig];
            const unsigned int b1 = xp[cc * 8 + tig + 4];
            mma_tf32(Cc[0][0], Cc[0][1], Cc[0][2], Cc[0][3],
                     afr[cc][0][0], afr[cc][0][1], afr[cc][0][2], afr[cc][0][3], b0, b1);
            mma_tf32(Cc[1][0], Cc[1][1], Cc[1][2], Cc[1][3],
                     afr[cc][1][0], afr[cc][1][1], afr[cc][1][2], afr[cc][1][3], b0, b1);
        }
    }

    for (int t = 0; t <= tmax; t++) {
        CP_WAIT2();
        __syncwarp();   // stage t+1 visible warp-wide

        // ── chain head: h(t-1) register transpose via shfl, then W_hh MMA ──
        {
            const float a0h0 = __shfl_sync(0xffffffffu, h0, srcA);
            const float a0h1 = __shfl_sync(0xffffffffu, h1, srcA);
            const float b0h0 = __shfl_sync(0xffffffffu, h0, srcB);
            const float b0h1 = __shfl_sync(0xffffffffu, h1, srcB);
            const unsigned int hb0 = __float_as_uint(oddp ? a0h1 : a0h0);
            const unsigned int hb1 = __float_as_uint(oddp ? b0h1 : b0h0);
            mma_tf32(Cc[0][0], Cc[0][1], Cc[0][2], Cc[0][3],
                     afr[6][0][0], afr[6][0][1], afr[6][0][2], afr[6][0][3], hb0, hb1);
            mma_tf32(Cc[1][0], Cc[1][1], Cc[1][2], Cc[1][3],
                     afr[6][1][0], afr[6][1][1], afr[6][1][2], afr[6][1][3], hb0, hb1);
        }

        // ── independent: Cn = bias + W_ih · x(t+1)  (fills chain shadows) ──
        {
            const unsigned int* xp = (const unsigned int*)&sx[(t + 1) & (RING - 1)][grp][0];
            Cn[0][0] = bi_i; Cn[0][1] = bi_i; Cn[0][2] = bi_f; Cn[0][3] = bi_f;
            Cn[1][0] = bi_g; Cn[1][1] = bi_g; Cn[1][2] = bi_o; Cn[1][3] = bi_o;
            #pragma unroll
            for (int cc = 0; cc < 6; cc++) {
                const unsigned int b0 = xp[cc * 8 + tig];
                const unsigned int b1 = xp[cc * 8 + tig + 4];
                mma_tf32(Cn[0][0], Cn[0][1], Cn[0][2], Cn[0][3],
                         afr[cc][0][0], afr[cc][0][1], afr[cc][0][2], afr[cc][0][3], b0, b1);
                mma_tf32(Cn[1][0], Cn[1][1], Cn[1][2], Cn[1][3],
                         afr[cc][1][0], afr[cc][1][1], afr[cc][1][2], afr[cc][1][3], b0, b1);
            }
        }

        // prefetch stage t+4
        {
            const int tp = t + RING;
            #pragma unroll
            for (int s = 0; s < 3; s++) {
                cp16_pred(sbase + (unsigned int)(((tp & (RING - 1)) * STAGE_B)) + sdst[s],
                          xsrc[s] + (size_t)min(tp, plastS[s]) * 44,
                          pval[s] && (tp <= plastS[s]));
            }
            CP_COMMIT();
        }

        // ── chain tail: activations + cell + h (all lane-local) ──
        const float i0 = fmaf(0.5f, fast_tanh(Cc[0][0]), 0.5f);
        const float i1 = fmaf(0.5f, fast_tanh(Cc[0][1]), 0.5f);
        const float f0 = fmaf(0.5f, fast_tanh(Cc[0][2]), 0.5f);
        const float f1 = fmaf(0.5f, fast_tanh(Cc[0][3]), 0.5f);
        const float g0 = fast_tanh(Cc[1][0]);
        const float g1 = fast_tanh(Cc[1][1]);
        const float o0 = fmaf(0.5f, fast_tanh(Cc[1][2]), 0.5f);
        const float o1 = fmaf(0.5f, fast_tanh(Cc[1][3]), 0.5f);

        cc0 = fmaf(f0, cc0, i0 * g0);
        cc1 = fmaf(f1, cc1, i1 * g1);
        h0 = o0 * fast_tanh(cc0);
        h1 = o1 * fast_tanh(cc1);

        if (t == last0) *out0 = h0;
        if (t == last1) *out1 = h1;

        // Cc <- Cn
        Cc[0][0] = Cn[0][0]; Cc[0][1] = Cn[0][1]; Cc[0][2] = Cn[0][2]; Cc[0][3] = Cn[0][3];
        Cc[1][0] = Cn[1][0]; Cc[1][1] = Cn[1][1]; Cc[1][2] = Cn[1][2]; Cc[1][3] = Cn[1][3];
    }
}

// ─────────────────────────────────────────────────────────────────────────────
// Finalize: per-path fc dot -> smem; counts + block scan -> segment sums;
// shfl softmax. One 1024-thread block.
// ─────────────────────────────────────────────────────────────────────────────
__global__ void __launch_bounds__(NGROUPS)
finalize_kernel(const int* __restrict__ group_ids,
                const float* __restrict__ fc_W,
                const float* __restrict__ fc_b,
                float* __restrict__ out)
{
    __shared__ float sdot[NPATHS];
    __shared__ int   scnt[NGROUPS];
    __shared__ int   sstart[NGROUPS];
    __shared__ int   wsum[32];
    __shared__ float warpred[32];
    __shared__ float bc;

    const int tid = threadIdx.x;
    const int wid = tid >> 5;
    const int lid = tid & 31;

    float w[8];
    #pragma unroll
    for (int j = 0; j < 8; j++) w[j] = fc_W[j];

    scnt[tid] = 0;
    __syncthreads();

    #pragma unroll
    for (int r = 0; r < NPATHS / NGROUPS; r++) {
        const int i = tid + r * NGROUPS;
        const float4* hp = (const float4*)(g_hlast + i * H_DIM);
        float4 h0 = hp[0], h1 = hp[1];
        float s = h0.x * w[0];
        s = fmaf(h0.y, w[1], s);
        s = fmaf(h0.z, w[2], s);
        s = fmaf(h0.w, w[3], s);
        s = fmaf(h1.x, w[4], s);
        s = fmaf(h1.y, w[5], s);
        s = fmaf(h1.z, w[6], s);
        s = fmaf(h1.w, w[7], s);
        sdot[i] = s;
        atomicAdd(&scnt[group_ids[i]], 1);
    }
    __syncthreads();

    const int myc = scnt[tid];
    int inc = myc;
    #pragma unroll
    for (int d = 1; d < 32; d <<= 1) {
        int n = __shfl_up_sync(0xffffffffu, inc, d);
        if (lid >= d) inc += n;
    }
    if (lid == 31) wsum[wid] = inc;
    __syncthreads();
    if (wid == 0) {
        int v = wsum[lid];
        int iv = v;
        #pragma unroll
        for (int d = 1; d < 32; d <<= 1) {
            int n = __shfl_up_sync(0xffffffffu, iv, d);
            if (lid >= d) iv += n;
        }
        wsum[lid] = iv - v;
    }
    __syncthreads();
    sstart[tid] = inc - myc + wsum[wid];
    __syncthreads();

    float logit = fc_b[0];
    {
        const int s = sstart[tid];
        const int e = s + myc;
        for (int i = s; i < e; i++) logit += sdot[i];
    }

    float m = logit;
    #pragma unroll
    for (int off = 16; off > 0; off >>= 1) m = fmaxf(m, __shfl_xor_sync(0xffffffffu, m, off));
    if (lid == 0) warpred[wid] = m;
    __syncthreads();
    if (wid == 0) {
        float v = warpred[lid];
        #pragma unroll
        for (int off = 16; off > 0; off >>= 1) v = fmaxf(v, __shfl_xor_sync(0xffffffffu, v, off));
        if (lid == 0) bc = v;
    }
    __syncthreads();
    const float mx = bc;

    const float e = __expf(logit - mx);

    float s = e;
    #pragma unroll
    for (int off = 16; off > 0; off >>= 1) s += __shfl_xor_sync(0xffffffffu, s, off);
    __syncthreads();
    if (lid == 0) warpred[wid] = s;
    __syncthreads();
    if (wid == 0) {
        float v = warpred[lid];
        #pragma unroll
        for (int off = 16; off > 0; off >>= 1) v += __shfl_xor_sync(0xffffffffu, v, off);
        if (lid == 0) bc = v;
    }
    __syncthreads();

    out[tid] = e * fast_rcp(bc);
}

extern "C" void kernel_launch(void* const* d_in, const int* in_sizes, int n_in,
                              void* d_out, int out_size)
{
    const float* x      = (const float*)d_in[0];
    const float* W_ih   = (const float*)d_in[1];
    const float* W_hh   = (const float*)d_in[2];
    const float* b_ih   = (const float*)d_in[3];
    const float* b_hh   = (const float*)d_in[4];
    const float* fc_W   = (const float*)d_in[5];
    const float* fc_b   = (const float*)d_in[6];
    const int*   last_i = (const int*)d_in[7];
    const int*   gids   = (const int*)d_in[8];
    float*       out    = (float*)d_out;

    sort_kernel<<<1, 1024>>>(last_i);
    lstm_kernel<<<NBLK, 32>>>(x, W_ih, W_hh, b_ih, b_hh, last_i);
    finalize_kernel<<<1, NGROUPS>>>(gids, fc_W, fc_b, out);
}

// round 16
// speedup vs baseline: 1.6750x; 1.0086x over previous
#include <cuda_runtime.h>
#include <cstdint>

#define T_DIM 256
#define D_DIM 44
#define H_DIM 8
#define NPATHS 8192
#define NGROUPS 1024
#define RING 4
#define PPW 8                         // paths per warp
#define NBLK (NPATHS / PPW)           // 1024
#define SIDE_F 52                     // floats per path-side in ring (conflict-free stride)
#define STAGE_B (PPW * SIDE_F * 4)    // bytes per ring stage

// scratch
__device__ float g_hlast[NPATHS * H_DIM];
__device__ int   g_order[NPATHS];

__device__ __forceinline__ float fast_rcp(float x) {
    float r; asm("rcp.approx.f32 %0, %1;" : "=f"(r) : "f"(x)); return r;
}
__device__ __forceinline__ float fast_tanh(float x) {
    float r; asm("tanh.approx.f32 %0, %1;" : "=f"(r) : "f"(x)); return r;
}
__device__ __forceinline__ unsigned int to_tf32(float x) {
    unsigned int r; asm("cvt.rna.tf32.f32 %0, %1;" : "=r"(r) : "f"(x)); return r;
}
__device__ __forceinline__ void mma_tf32(float& c0, float& c1, float& c2, float& c3,
                                         unsigned int a0, unsigned int a1,
                                         unsigned int a2, unsigned int a3,
                                         unsigned int b0, unsigned int b1) {
    asm("mma.sync.aligned.m16n8k8.row.col.f32.tf32.tf32.f32 "
        "{%0,%1,%2,%3}, {%4,%5,%6,%7}, {%8,%9}, {%0,%1,%2,%3};"
        : "+f"(c0), "+f"(c1), "+f"(c2), "+f"(c3)
        : "r"(a0), "r"(a1), "r"(a2), "r"(a3), "r"(b0), "r"(b1));
}

__device__ __forceinline__ unsigned int smem_u32(const void* p) {
    return (unsigned int)__cvta_generic_to_shared(p);
}
__device__ __forceinline__ void cp16_pred(unsigned int dst, const void* src, bool pred) {
    asm volatile(
        "{ .reg .pred q; setp.ne.u32 q, %2, 0;"
        " @q cp.async.ca.shared.global [%0], [%1], 16; }"
        :: "r"(dst), "l"(src), "r"((int)pred));
}
#define CP_COMMIT() asm volatile("cp.async.commit_group;" ::: "memory")
#define CP_WAIT2()  asm volatile("cp.async.wait_group 2;" ::: "memory")

// ─────────────────────────────────────────────────────────────────────────────
// Counting sort by last_idx DESCENDING (parallel scan, int4-vectorized).
// ─────────────────────────────────────────────────────────────────────────────
__global__ void __launch_bounds__(1024)
sort_kernel(const int* __restrict__ last_idx)
{
    __shared__ int cnt[256];
    __shared__ int soff[256];
    __shared__ int wsum[8];
    __shared__ int wpre[8];
    const int tid = threadIdx.x;

    if (tid < 256) cnt[tid] = 0;
    __syncthreads();
    const int4* li4 = (const int4*)last_idx;
    #pragma unroll
    for (int i = tid; i < NPATHS / 4; i += 1024) {
        int4 v = li4[i];
        atomicAdd(&cnt[v.x], 1);
        atomicAdd(&cnt[v.y], 1);
        atomicAdd(&cnt[v.z], 1);
        atomicAdd(&cnt[v.w], 1);
    }
    __syncthreads();

    int v = 0;
    if (tid < 256) {
        const int r = tid;
        v = cnt[255 - r];
        #pragma unroll
        for (int d = 1; d < 32; d <<= 1) {
            int n = __shfl_up_sync(0xffffffffu, v, d);
            if ((r & 31) >= d) v += n;
        }
        if ((r & 31) == 31) wsum[r >> 5] = v;
    }
    __syncthreads();
    if (tid == 0) {
        int run = 0;
        #pragma unroll
        for (int w = 0; w < 8; w++) { wpre[w] = run; run += wsum[w]; }
    }
    __syncthreads();
    if (tid < 256) {
        const int r = tid;
        soff[255 - r] = v - cnt[255 - r] + wpre[r >> 5];
    }
    __syncthreads();
    if (tid < 256) cnt[tid] = 0;
    __syncthreads();

    #pragma unroll
    for (int i = tid; i < NPATHS / 4; i += 1024) {
        int4 L = li4[i];
        const int base = i * 4;
        g_order[soff[L.x] + atomicAdd(&cnt[L.x], 1)] = base + 0;
        g_order[soff[L.y] + atomicAdd(&cnt[L.y], 1)] = base + 1;
        g_order[soff[L.z] + atomicAdd(&cnt[L.z], 1)] = base + 2;
        g_order[soff[L.w] + atomicAdd(&cnt[L.w], 1)] = base + 3;
    }
}

// ─────────────────────────────────────────────────────────────────────────────
// LSTM via tf32 MMA. Critical-path minimized:
//  - x-dot split into TWO independent 3-MMA chains (Cna, Cnb), merged off-chain
//  - CP_WAIT/syncwarp moved AFTER the recurrence head+tail (they touch no smem)
//  - h redistributed by register-transpose shfl; raw fp32 bits as tf32 B operands
// ─────────────────────────────────────────────────────────────────────────────
__global__ void __launch_bounds__(32)
lstm_kernel(const float* __restrict__ x,
            const float* __restrict__ W_ih,
            const float* __restrict__ W_hh,
            const float* __restrict__ b_ih,
            const float* __restrict__ b_hh,
            const int* __restrict__ last_idx)
{
    __shared__ float sx[RING][PPW][SIDE_F];   // x ring (floats 44..51 = zero pad)
    __shared__ float wext[32][56];            // [gate row][k] pre-scaled

    const int lane = threadIdx.x;
    const int grp  = lane >> 2;   // 0..7
    const int tig  = lane & 3;    // 0..3
    const int* ord = g_order + PPW * blockIdx.x;

    // this lane's two paths (C cols 2*tig, 2*tig+1)
    const int p0 = ord[2 * tig];
    const int p1 = ord[2 * tig + 1];
    const int last0 = last_idx[p0];
    const int last1 = last_idx[p1];
    int tmax = max(last0, last1);
    tmax = max(tmax, __shfl_xor_sync(0xffffffffu, tmax, 1));
    tmax = max(tmax, __shfl_xor_sync(0xffffffffu, tmax, 2));

    // build W_ext row (this lane's gate row), activation scale folded in
    {
        const bool isg = (lane >= 16) && (lane < 24);
        const float m = isg ? 1.0f : 0.5f;
        const float* wr = W_ih + lane * 44;
        #pragma unroll 4
        for (int k = 0; k < 44; k++) wext[lane][k] = wr[k] * m;
        wext[lane][44] = 0.f; wext[lane][45] = 0.f;
        wext[lane][46] = 0.f; wext[lane][47] = 0.f;
        const float* wh = W_hh + lane * 8;
        #pragma unroll
        for (int q = 0; q < 8; q++) wext[lane][48 + q] = wh[q] * m;
    }
    // biases (scaled) for rows grp(+8/16/24)
    const float bi_i = (b_ih[grp]      + b_hh[grp])      * 0.5f;
    const float bi_f = (b_ih[grp + 8]  + b_hh[grp + 8])  * 0.5f;
    const float bi_g = (b_ih[grp + 16] + b_hh[grp + 16]);
    const float bi_o = (b_ih[grp + 24] + b_hh[grp + 24]) * 0.5f;

    // zero ring pads (floats 44..51 of each side)
    {
        const int st = lane >> 3, sd = lane & 7;
        float4* pad = (float4*)&sx[st][sd][44];
        pad[0] = make_float4(0, 0, 0, 0);
        pad[1] = make_float4(0, 0, 0, 0);
    }
    __syncwarp();

    // A fragments (weights), in registers, tf32 (rounded once)
    unsigned int afr[7][2][4];
    #pragma unroll
    for (int cc = 0; cc < 7; cc++) {
        #pragma unroll
        for (int hh = 0; hh < 2; hh++) {
            const int r0 = hh * 16 + grp;
            afr[cc][hh][0] = to_tf32(wext[r0][cc * 8 + tig]);
            afr[cc][hh][1] = to_tf32(wext[r0 + 8][cc * 8 + tig]);
            afr[cc][hh][2] = to_tf32(wext[r0][cc * 8 + tig + 4]);
            afr[cc][hh][3] = to_tf32(wext[r0 + 8][cc * 8 + tig + 4]);
        }
    }

    // h shuffle sources (register transpose, validated in R14)
    const int srcA = tig * 4 + (grp >> 1);
    const int srcB = srcA + 16;
    const bool oddp = (grp & 1);

    // loader slots: 88 (path, quad) pairs over 3 rounds of 32 lanes
    const float* xsrc[3];
    int  plastS[3];
    unsigned int sdst[3];
    bool pval[3];
    #pragma unroll
    for (int s = 0; s < 3; s++) {
        const int i = lane + 32 * s;
        pval[s] = (i < 88);
        const int pi = pval[s] ? (i / 11) : 0;
        const int qi = pval[s] ? (i % 11) : 0;
        const int pp = ord[pi];
        xsrc[s]   = x + (size_t)pp * T_DIM * D_DIM + qi * 4;
        plastS[s] = last_idx[pp];
        sdst[s]   = (unsigned int)((pi * SIDE_F + qi * 4) * 4);
    }
    const unsigned int sbase = smem_u32(&sx[0][0][0]);

    // prologue: fill stages 0..3
    #pragma unroll
    for (int p = 0; p < RING; p++) {
        #pragma unroll
        for (int s = 0; s < 3; s++) {
            const int row = min(p, plastS[s]);
            cp16_pred(sbase + (unsigned int)(p * STAGE_B) + sdst[s],
                      xsrc[s] + (size_t)row * 44, pval[s]);
        }
        CP_COMMIT();
    }

    float cc0 = 0.f, cc1 = 0.f;
    float h0 = 0.f, h1 = 0.f;
    float* out0 = g_hlast + p0 * H_DIM + grp;
    float* out1 = g_hlast + p1 * H_DIM + grp;

    float Cc[2][4];          // merged gate pre-activation for step t (before h-MMA)
    float Cna[2][4], Cnb[2][4];

    // initial split dot for step 0 (stage 0), then merge
    CP_WAIT2();
    __syncwarp();
    {
        const unsigned int* xp = (const unsigned int*)&sx[0][grp][0];
        Cna[0][0] = bi_i; Cna[0][1] = bi_i; Cna[0][2] = bi_f; Cna[0][3] = bi_f;
        Cna[1][0] = bi_g; Cna[1][1] = bi_g; Cna[1][2] = bi_o; Cna[1][3] = bi_o;
        #pragma unroll
        for (int j = 0; j < 2; j++)
            #pragma unroll
            for (int q = 0; q < 4; q++) Cnb[j][q] = 0.f;
        #pragma unroll
        for (int cc = 0; cc < 3; cc++) {
            const unsigned int b0 = xp[cc * 8 + tig];
            const unsigned int b1 = xp[cc * 8 + tig + 4];
            mma_tf32(Cna[0][0], Cna[0][1], Cna[0][2], Cna[0][3],
                     afr[cc][0][0], afr[cc][0][1], afr[cc][0][2], afr[cc][0][3], b0, b1);
            mma_tf32(Cna[1][0], Cna[1][1], Cna[1][2], Cna[1][3],
                     afr[cc][1][0], afr[cc][1][1], afr[cc][1][2], afr[cc][1][3], b0, b1);
        }
        #pragma unroll
        for (int cc = 3; cc < 6; cc++) {
            const unsigned int b0 = xp[cc * 8 + tig];
            const unsigned int b1 = xp[cc * 8 + tig + 4];
            mma_tf32(Cnb[0][0], Cnb[0][1], Cnb[0][2], Cnb[0][3],
                     afr[cc][0][0], afr[cc][0][1], afr[cc][0][2], afr[cc][0][3], b0, b1);
            mma_tf32(Cnb[1][0], Cnb[1][1], Cnb[1][2], Cnb[1][3],
                     afr[cc][1][0], afr[cc][1][1], afr[cc][1][2], afr[cc][1][3], b0, b1);
        }
        #pragma unroll
        for (int j = 0; j < 2; j++)
            #pragma unroll
            for (int q = 0; q < 4; q++) Cc[j][q] = Cna[j][q] + Cnb[j][q];
    }

    for (int t = 0; t <= tmax; t++) {
        // ── chain head (NO smem dependency): h transpose + W_hh MMA into Cc ──
        {
            const float a0h0 = __shfl_sync(0xffffffffu, h0, srcA);
            const float a0h1 = __shfl_sync(0xffffffffu, h1, srcA);
            const float b0h0 = __shfl_sync(0xffffffffu, h0, srcB);
            const float b0h1 = __shfl_sync(0xffffffffu, h1, srcB);
            const unsigned int hb0 = __float_as_uint(oddp ? a0h1 : a0h0);
            const unsigned int hb1 = __float_as_uint(oddp ? b0h1 : b0h0);
            mma_tf32(Cc[0][0], Cc[0][1], Cc[0][2], Cc[0][3],
                     afr[6][0][0], afr[6][0][1], afr[6][0][2], afr[6][0][3], hb0, hb1);
            mma_tf32(Cc[1][0], Cc[1][1], Cc[1][2], Cc[1][3],
                     afr[6][1][0], afr[6][1][1], afr[6][1][2], afr[6][1][3], hb0, hb1);
        }

        // ── chain tail: activations + cell + h ──
        {
            const float i0 = fmaf(0.5f, fast_tanh(Cc[0][0]), 0.5f);
            const float i1 = fmaf(0.5f, fast_tanh(Cc[0][1]), 0.5f);
            const float f0 = fmaf(0.5f, fast_tanh(Cc[0][2]), 0.5f);
            const float f1 = fmaf(0.5f, fast_tanh(Cc[0][3]), 0.5f);
            const float g0 = fast_tanh(Cc[1][0]);
            const float g1 = fast_tanh(Cc[1][1]);
            const float o0 = fmaf(0.5f, fast_tanh(Cc[1][2]), 0.5f);
            const float o1 = fmaf(0.5f, fast_tanh(Cc[1][3]), 0.5f);

            cc0 = fmaf(f0, cc0, i0 * g0);
            cc1 = fmaf(f1, cc1, i1 * g1);
            h0 = o0 * fast_tanh(cc0);
            h1 = o1 * fast_tanh(cc1);

            if (t == last0) *out0 = h0;
            if (t == last1) *out1 = h1;
        }

        // ── barrier for x(t+1) visibility (overlaps the chain above) ──
        CP_WAIT2();
        __syncwarp();

        // ── split x-dot for step t+1: two independent 3-MMA chains ──
        {
            const unsigned int* xp = (const unsigned int*)&sx[(t + 1) & (RING - 1)][grp][0];
            Cna[0][0] = bi_i; Cna[0][1] = bi_i; Cna[0][2] = bi_f; Cna[0][3] = bi_f;
            Cna[1][0] = bi_g; Cna[1][1] = bi_g; Cna[1][2] = bi_o; Cna[1][3] = bi_o;
            #pragma unroll
            for (int j = 0; j < 2; j++)
                #pragma unroll
                for (int q = 0; q < 4; q++) Cnb[j][q] = 0.f;
            #pragma unroll
            for (int cc = 0; cc < 3; cc++) {
                const unsigned int b0 = xp[cc * 8 + tig];
                const unsigned int b1 = xp[cc * 8 + tig + 4];
                mma_tf32(Cna[0][0], Cna[0][1], Cna[0][2], Cna[0][3],
                         afr[cc][0][0], afr[cc][0][1], afr[cc][0][2], afr[cc][0][3], b0, b1);
                mma_tf32(Cna[1][0], Cna[1][1], Cna[1][2], Cna[1][3],
                         afr[cc][1][0], afr[cc][1][1], afr[cc][1][2], afr[cc][1][3], b0, b1);
            }
            #pragma unroll
            for (int cc = 3; cc < 6; cc++) {
                const unsigned int b0 = xp[cc * 8 + tig];
                const unsigned int b1 = xp[cc * 8 + tig + 4];
                mma_tf32(Cnb[0][0], Cnb[0][1], Cnb[0][2], Cnb[0][3],
                         afr[cc][0][0], afr[cc][0][1], afr[cc][0][2], afr[cc][0][3], b0, b1);
                mma_tf32(Cnb[1][0], Cnb[1][1], Cnb[1][2], Cnb[1][3],
                         afr[cc][1][0], afr[cc][1][1], afr[cc][1][2], afr[cc][1][3], b0, b1);
            }
        }

        // prefetch stage t+4
        {
            const int tp = t + RING;
            #pragma unroll
            for (int s = 0; s < 3; s++) {
                cp16_pred(sbase + (unsigned int)(((tp & (RING - 1)) * STAGE_B)) + sdst[s],
                          xsrc[s] + (size_t)min(tp, plastS[s]) * 44,
                          pval[s] && (tp <= plastS[s]));
            }
            CP_COMMIT();
        }

        // merge (off critical path: both halves are long since complete)
        #pragma unroll
        for (int j = 0; j < 2; j++)
            #pragma unroll
            for (int q = 0; q < 4; q++) Cc[j][q] = Cna[j][q] + Cnb[j][q];
    }
}

// ─────────────────────────────────────────────────────────────────────────────
// Finalize: per-path fc dot -> smem; counts + block scan -> segment sums;
// shfl softmax. One 1024-thread block.
// ─────────────────────────────────────────────────────────────────────────────
__global__ void __launch_bounds__(NGROUPS)
finalize_kernel(const int* __restrict__ group_ids,
                const float* __restrict__ fc_W,
                const float* __restrict__ fc_b,
                float* __restrict__ out)
{
    __shared__ float sdot[NPATHS];
    __shared__ int   scnt[NGROUPS];
    __shared__ int   sstart[NGROUPS];
    __shared__ int   wsum[32];
    __shared__ float warpred[32];
    __shared__ float bc;

    const int tid = threadIdx.x;
    const int wid = tid >> 5;
    const int lid = tid & 31;

    float w[8];
    #pragma unroll
    for (int j = 0; j < 8; j++) w[j] = fc_W[j];

    scnt[tid] = 0;
    __syncthreads();

    #pragma unroll
    for (int r = 0; r < NPATHS / NGROUPS; r++) {
        const int i = tid + r * NGROUPS;
        const float4* hp = (const float4*)(g_hlast + i * H_DIM);
        float4 h0 = hp[0], h1 = hp[1];
        float s = h0.x * w[0];
        s = fmaf(h0.y, w[1], s);
        s = fmaf(h0.z, w[2], s);
        s = fmaf(h0.w, w[3], s);
        s = fmaf(h1.x, w[4], s);
        s = fmaf(h1.y, w[5], s);
        s = fmaf(h1.z, w[6], s);
        s = fmaf(h1.w, w[7], s);
        sdot[i] = s;
        atomicAdd(&scnt[group_ids[i]], 1);
    }
    __syncthreads();

    const int myc = scnt[tid];
    int inc = myc;
    #pragma unroll
    for (int d = 1; d < 32; d <<= 1) {
        int n = __shfl_up_sync(0xffffffffu, inc, d);
        if (lid >= d) inc += n;
    }
    if (lid == 31) wsum[wid] = inc;
    __syncthreads();
    if (wid == 0) {
        int v = wsum[lid];
        int iv = v;
        #pragma unroll
        for (int d = 1; d < 32; d <<= 1) {
            int n = __shfl_up_sync(0xffffffffu, iv, d);
            if (lid >= d) iv += n;
        }
        wsum[lid] = iv - v;
    }
    __syncthreads();
    sstart[tid] = inc - myc + wsum[wid];
    __syncthreads();

    float logit = fc_b[0];
    {
        const int s = sstart[tid];
        const int e = s + myc;
        for (int i = s; i < e; i++) logit += sdot[i];
    }

    float m = logit;
    #pragma unroll
    for (int off = 16; off > 0; off >>= 1) m = fmaxf(m, __shfl_xor_sync(0xffffffffu, m, off));
    if (lid == 0) warpred[wid] = m;
    __syncthreads();
    if (wid == 0) {
        float v = warpred[lid];
        #pragma unroll
        for (int off = 16; off > 0; off >>= 1) v = fmaxf(v, __shfl_xor_sync(0xffffffffu, v, off));
        if (lid == 0) bc = v;
    }
    __syncthreads();
    const float mx = bc;

    const float e = __expf(logit - mx);

    float s = e;
    #pragma unroll
    for (int off = 16; off > 0; off >>= 1) s += __shfl_xor_sync(0xffffffffu, s, off);
    __syncthreads();
    if (lid == 0) warpred[wid] = s;
    __syncthreads();
    if (wid == 0) {
        float v = warpred[lid];
        #pragma unroll
        for (int off = 16; off > 0; off >>= 1) v += __shfl_xor_sync(0xffffffffu, v, off);
        if (lid == 0) bc = v;
    }
    __syncthreads();

    out[tid] = e * fast_rcp(bc);
}

extern "C" void kernel_launch(void* const* d_in, const int* in_sizes, int n_in,
                              void* d_out, int out_size)
{
    const float* x      = (const float*)d_in[0];
    const float* W_ih   = (const float*)d_in[1];
    const float* W_hh   = (const float*)d_in[2];
    const float* b_ih   = (const float*)d_in[3];
    const float* b_hh   = (const float*)d_in[4];
    const float* fc_W   = (const float*)d_in[5];
    const float* fc_b   = (const float*)d_in[6];
    const int*   last_i = (const int*)d_in[7];
    const int*   gids   = (const int*)d_in[8];
    float*       out    = (float*)d_out;

    sort_kernel<<<1, 1024>>>(last_i);
    lstm_kernel<<<NBLK, 32>>>(x, W_ih, W_hh, b_ih, b_hh, last_i);
    finalize_kernel<<<1, NGROUPS>>>(gids, fc_W, fc_b, out);
}

// round 17
// speedup vs baseline: 1.7130x; 1.0227x over previous
#include <cuda_runtime.h>
#include <cstdint>

#define T_DIM 256
#define D_DIM 44
#define H_DIM 8
#define NPATHS 8192
#define NGROUPS 1024
#define RING 8
#define PPW 8                         // paths per warp
#define NBLK (NPATHS / PPW)           // 1024
#define SIDE_F 52                     // floats per path-side in ring (conflict-free stride)
#define STAGE_B (PPW * SIDE_F * 4)    // bytes per ring stage

// scratch
__device__ float g_hlast[NPATHS * H_DIM];
__device__ int   g_order[NPATHS];

__device__ __forceinline__ float fast_rcp(float x) {
    float r; asm("rcp.approx.f32 %0, %1;" : "=f"(r) : "f"(x)); return r;
}
__device__ __forceinline__ float fast_tanh(float x) {
    float r; asm("tanh.approx.f32 %0, %1;" : "=f"(r) : "f"(x)); return r;
}
__device__ __forceinline__ unsigned int to_tf32(float x) {
    unsigned int r; asm("cvt.rna.tf32.f32 %0, %1;" : "=r"(r) : "f"(x)); return r;
}
__device__ __forceinline__ void mma_tf32(float& c0, float& c1, float& c2, float& c3,
                                         unsigned int a0, unsigned int a1,
                                         unsigned int a2, unsigned int a3,
                                         unsigned int b0, unsigned int b1) {
    asm("mma.sync.aligned.m16n8k8.row.col.f32.tf32.tf32.f32 "
        "{%0,%1,%2,%3}, {%4,%5,%6,%7}, {%8,%9}, {%0,%1,%2,%3};"
        : "+f"(c0), "+f"(c1), "+f"(c2), "+f"(c3)
        : "r"(a0), "r"(a1), "r"(a2), "r"(a3), "r"(b0), "r"(b1));
}

__device__ __forceinline__ unsigned int smem_u32(const void* p) {
    return (unsigned int)__cvta_generic_to_shared(p);
}
__device__ __forceinline__ void cp16_pred(unsigned int dst, const void* src, bool pred) {
    asm volatile(
        "{ .reg .pred q; setp.ne.u32 q, %2, 0;"
        " @q cp.async.ca.shared.global [%0], [%1], 16; }"
        :: "r"(dst), "l"(src), "r"((int)pred));
}
#define CP_COMMIT() asm volatile("cp.async.commit_group;" ::: "memory")
#define CP_WAIT6()  asm volatile("cp.async.wait_group 6;" ::: "memory")

// ─────────────────────────────────────────────────────────────────────────────
// Counting sort by last_idx DESCENDING (parallel scan, int4-vectorized).
// ─────────────────────────────────────────────────────────────────────────────
__global__ void __launch_bounds__(1024)
sort_kernel(const int* __restrict__ last_idx)
{
    __shared__ int cnt[256];
    __shared__ int soff[256];
    __shared__ int wsum[8];
    __shared__ int wpre[8];
    const int tid = threadIdx.x;

    if (tid < 256) cnt[tid] = 0;
    __syncthreads();
    const int4* li4 = (const int4*)last_idx;
    #pragma unroll
    for (int i = tid; i < NPATHS / 4; i += 1024) {
        int4 v = li4[i];
        atomicAdd(&cnt[v.x], 1);
        atomicAdd(&cnt[v.y], 1);
        atomicAdd(&cnt[v.z], 1);
        atomicAdd(&cnt[v.w], 1);
    }
    __syncthreads();

    int v = 0;
    if (tid < 256) {
        const int r = tid;
        v = cnt[255 - r];
        #pragma unroll
        for (int d = 1; d < 32; d <<= 1) {
            int n = __shfl_up_sync(0xffffffffu, v, d);
            if ((r & 31) >= d) v += n;
        }
        if ((r & 31) == 31) wsum[r >> 5] = v;
    }
    __syncthreads();
    if (tid == 0) {
        int run = 0;
        #pragma unroll
        for (int w = 0; w < 8; w++) { wpre[w] = run; run += wsum[w]; }
    }
    __syncthreads();
    if (tid < 256) {
        const int r = tid;
        soff[255 - r] = v - cnt[255 - r] + wpre[r >> 5];
    }
    __syncthreads();
    if (tid < 256) cnt[tid] = 0;
    __syncthreads();

    #pragma unroll
    for (int i = tid; i < NPATHS / 4; i += 1024) {
        int4 L = li4[i];
        const int base = i * 4;
        g_order[soff[L.x] + atomicAdd(&cnt[L.x], 1)] = base + 0;
        g_order[soff[L.y] + atomicAdd(&cnt[L.y], 1)] = base + 1;
        g_order[soff[L.z] + atomicAdd(&cnt[L.z], 1)] = base + 2;
        g_order[soff[L.w] + atomicAdd(&cnt[L.w], 1)] = base + 3;
    }
}

// ─────────────────────────────────────────────────────────────────────────────
// LSTM via tf32 MMA. Deep prefetch pipeline: 8-stage x ring, wait_group 6 ->
// SIX steps of DRAM cover (tests/removes the loaded-latency wall). Chain as in
// R16 (split 3-MMA x-dot, shfl h-transpose, barrier after the chain).
// ─────────────────────────────────────────────────────────────────────────────
__global__ void __launch_bounds__(32)
lstm_kernel(const float* __restrict__ x,
            const float* __restrict__ W_ih,
            const float* __restrict__ W_hh,
            const float* __restrict__ b_ih,
            const float* __restrict__ b_hh,
            const int* __restrict__ last_idx)
{
    __shared__ float sx[RING][PPW][SIDE_F];   // x ring (floats 44..51 = zero pad)
    __shared__ float wext[32][56];            // [gate row][k] pre-scaled

    const int lane = threadIdx.x;
    const int grp  = lane >> 2;   // 0..7
    const int tig  = lane & 3;    // 0..3
    const int* ord = g_order + PPW * blockIdx.x;

    // this lane's two paths (C cols 2*tig, 2*tig+1)
    const int p0 = ord[2 * tig];
    const int p1 = ord[2 * tig + 1];
    const int last0 = last_idx[p0];
    const int last1 = last_idx[p1];
    int tmax = max(last0, last1);
    tmax = max(tmax, __shfl_xor_sync(0xffffffffu, tmax, 1));
    tmax = max(tmax, __shfl_xor_sync(0xffffffffu, tmax, 2));

    // build W_ext row (this lane's gate row), activation scale folded in
    {
        const bool isg = (lane >= 16) && (lane < 24);
        const float m = isg ? 1.0f : 0.5f;
        const float* wr = W_ih + lane * 44;
        #pragma unroll 4
        for (int k = 0; k < 44; k++) wext[lane][k] = wr[k] * m;
        wext[lane][44] = 0.f; wext[lane][45] = 0.f;
        wext[lane][46] = 0.f; wext[lane][47] = 0.f;
        const float* wh = W_hh + lane * 8;
        #pragma unroll
        for (int q = 0; q < 8; q++) wext[lane][48 + q] = wh[q] * m;
    }
    // biases (scaled) for rows grp(+8/16/24)
    const float bi_i = (b_ih[grp]      + b_hh[grp])      * 0.5f;
    const float bi_f = (b_ih[grp + 8]  + b_hh[grp + 8])  * 0.5f;
    const float bi_g = (b_ih[grp + 16] + b_hh[grp + 16]);
    const float bi_o = (b_ih[grp + 24] + b_hh[grp + 24]) * 0.5f;

    // zero ring pads (floats 44..51 of every stage/side)
    #pragma unroll
    for (int st = lane >> 3; st < RING; st += 4) {
        float4* pad = (float4*)&sx[st][lane & 7][44];
        pad[0] = make_float4(0, 0, 0, 0);
        pad[1] = make_float4(0, 0, 0, 0);
    }
    __syncwarp();

    // A fragments (weights), in registers, tf32 (rounded once)
    unsigned int afr[7][2][4];
    #pragma unroll
    for (int cc = 0; cc < 7; cc++) {
        #pragma unroll
        for (int hh = 0; hh < 2; hh++) {
            const int r0 = hh * 16 + grp;
            afr[cc][hh][0] = to_tf32(wext[r0][cc * 8 + tig]);
            afr[cc][hh][1] = to_tf32(wext[r0 + 8][cc * 8 + tig]);
            afr[cc][hh][2] = to_tf32(wext[r0][cc * 8 + tig + 4]);
            afr[cc][hh][3] = to_tf32(wext[r0 + 8][cc * 8 + tig + 4]);
        }
    }

    // h shuffle sources (register transpose)
    const int srcA = tig * 4 + (grp >> 1);
    const int srcB = srcA + 16;
    const bool oddp = (grp & 1);

    // loader slots: 88 (path, quad) pairs over 3 rounds of 32 lanes
    const float* xsrc[3];
    int  plastS[3];
    unsigned int sdst[3];
    bool pval[3];
    #pragma unroll
    for (int s = 0; s < 3; s++) {
        const int i = lane + 32 * s;
        pval[s] = (i < 88);
        const int pi = pval[s] ? (i / 11) : 0;
        const int qi = pval[s] ? (i % 11) : 0;
        const int pp = ord[pi];
        xsrc[s]   = x + (size_t)pp * T_DIM * D_DIM + qi * 4;
        plastS[s] = last_idx[pp];
        sdst[s]   = (unsigned int)((pi * SIDE_F + qi * 4) * 4);
    }
    const unsigned int sbase = smem_u32(&sx[0][0][0]);

    // prologue: fill stages 0..7 (rows clamped so every slot holds valid data)
    #pragma unroll
    for (int p = 0; p < RING; p++) {
        #pragma unroll
        for (int s = 0; s < 3; s++) {
            const int row = min(p, plastS[s]);
            cp16_pred(sbase + (unsigned int)(p * STAGE_B) + sdst[s],
                      xsrc[s] + (size_t)row * 44, pval[s]);
        }
        CP_COMMIT();
    }

    float cc0 = 0.f, cc1 = 0.f;
    float h0 = 0.f, h1 = 0.f;
    float* out0 = g_hlast + p0 * H_DIM + grp;
    float* out1 = g_hlast + p1 * H_DIM + grp;

    float Cc[2][4];          // merged gate pre-activation for step t (before h-MMA)
    float Cna[2][4], Cnb[2][4];

    // initial split dot for step 0 (stage 0), then merge
    CP_WAIT6();              // stages 0,1 complete
    __syncwarp();
    {
        const unsigned int* xp = (const unsigned int*)&sx[0][grp][0];
        Cna[0][0] = bi_i; Cna[0][1] = bi_i; Cna[0][2] = bi_f; Cna[0][3] = bi_f;
        Cna[1][0] = bi_g; Cna[1][1] = bi_g; Cna[1][2] = bi_o; Cna[1][3] = bi_o;
        #pragma unroll
        for (int j = 0; j < 2; j++)
            #pragma unroll
            for (int q = 0; q < 4; q++) Cnb[j][q] = 0.f;
        #pragma unroll
        for (int cc = 0; cc < 3; cc++) {
            const unsigned int b0 = xp[cc * 8 + tig];
            const unsigned int b1 = xp[cc * 8 + tig + 4];
            mma_tf32(Cna[0][0], Cna[0][1], Cna[0][2], Cna[0][3],
                     afr[cc][0][0], afr[cc][0][1], afr[cc][0][2], afr[cc][0][3], b0, b1);
            mma_tf32(Cna[1][0], Cna[1][1], Cna[1][2], Cna[1][3],
                     afr[cc][1][0], afr[cc][1][1], afr[cc][1][2], afr[cc][1][3], b0, b1);
        }
        #pragma unroll
        for (int cc = 3; cc < 6; cc++) {
            const unsigned int b0 = xp[cc * 8 + tig];
            const unsigned int b1 = xp[cc * 8 + tig + 4];
            mma_tf32(Cnb[0][0], Cnb[0][1], Cnb[0][2], Cnb[0][3],
                     afr[cc][0][0], afr[cc][0][1], afr[cc][0][2], afr[cc][0][3], b0, b1);
            mma_tf32(Cnb[1][0], Cnb[1][1], Cnb[1][2], Cnb[1][3],
                     afr[cc][1][0], afr[cc][1][1], afr[cc][1][2], afr[cc][1][3], b0, b1);
        }
        #pragma unroll
        for (int j = 0; j < 2; j++)
            #pragma unroll
            for (int q = 0; q < 4; q++) Cc[j][q] = Cna[j][q] + Cnb[j][q];
    }

    for (int t = 0; t <= tmax; t++) {
        // ── chain head (no smem dependency): h transpose + W_hh MMA into Cc ──
        {
            const float a0h0 = __shfl_sync(0xffffffffu, h0, srcA);
            const float a0h1 = __shfl_sync(0xffffffffu, h1, srcA);
            const float b0h0 = __shfl_sync(0xffffffffu, h0, srcB);
            const float b0h1 = __shfl_sync(0xffffffffu, h1, srcB);
            const unsigned int hb0 = __float_as_uint(oddp ? a0h1 : a0h0);
            const unsigned int hb1 = __float_as_uint(oddp ? b0h1 : b0h0);
            mma_tf32(Cc[0][0], Cc[0][1], Cc[0][2], Cc[0][3],
                     afr[6][0][0], afr[6][0][1], afr[6][0][2], afr[6][0][3], hb0, hb1);
            mma_tf32(Cc[1][0], Cc[1][1], Cc[1][2], Cc[1][3],
                     afr[6][1][0], afr[6][1][1], afr[6][1][2], afr[6][1][3], hb0, hb1);
        }

        // ── chain tail: activations + cell + h ──
        {
            const float i0 = fmaf(0.5f, fast_tanh(Cc[0][0]), 0.5f);
            const float i1 = fmaf(0.5f, fast_tanh(Cc[0][1]), 0.5f);
            const float f0 = fmaf(0.5f, fast_tanh(Cc[0][2]), 0.5f);
            const float f1 = fmaf(0.5f, fast_tanh(Cc[0][3]), 0.5f);
            const float g0 = fast_tanh(Cc[1][0]);
            const float g1 = fast_tanh(Cc[1][1]);
            const float o0 = fmaf(0.5f, fast_tanh(Cc[1][2]), 0.5f);
            const float o1 = fmaf(0.5f, fast_tanh(Cc[1][3]), 0.5f);

            cc0 = fmaf(f0, cc0, i0 * g0);
            cc1 = fmaf(f1, cc1, i1 * g1);
            h0 = o0 * fast_tanh(cc0);
            h1 = o1 * fast_tanh(cc1);

            if (t == last0) *out0 = h0;
            if (t == last1) *out1 = h1;
        }

        // ── barrier for x(t+1) visibility (6 groups may stay in flight) ──
        CP_WAIT6();
        __syncwarp();

        // ── split x-dot for step t+1: two independent 3-MMA chains ──
        {
            const unsigned int* xp = (const unsigned int*)&sx[(t + 1) & (RING - 1)][grp][0];
            Cna[0][0] = bi_i; Cna[0][1] = bi_i; Cna[0][2] = bi_f; Cna[0][3] = bi_f;
            Cna[1][0] = bi_g; Cna[1][1] = bi_g; Cna[1][2] = bi_o; Cna[1][3] = bi_o;
            #pragma unroll
            for (int j = 0; j < 2; j++)
                #pragma unroll
                for (int q = 0; q < 4; q++) Cnb[j][q] = 0.f;
            #pragma unroll
            for (int cc = 0; cc < 3; cc++) {
                const unsigned int b0 = xp[cc * 8 + tig];
                const unsigned int b1 = xp[cc * 8 + tig + 4];
                mma_tf32(Cna[0][0], Cna[0][1], Cna[0][2], Cna[0][3],
                         afr[cc][0][0], afr[cc][0][1], afr[cc][0][2], afr[cc][0][3], b0, b1);
                mma_tf32(Cna[1][0], Cna[1][1], Cna[1][2], Cna[1][3],
                         afr[cc][1][0], afr[cc][1][1], afr[cc][1][2], afr[cc][1][3], b0, b1);
            }
            #pragma unroll
            for (int cc = 3; cc < 6; cc++) {
                const unsigned int b0 = xp[cc * 8 + tig];
                const unsigned int b1 = xp[cc * 8 + tig + 4];
                mma_tf32(Cnb[0][0], Cnb[0][1], Cnb[0][2], Cnb[0][3],
                         afr[cc][0][0], afr[cc][0][1], afr[cc][0][2], afr[cc][0][3], b0, b1);
                mma_tf32(Cnb[1][0], Cnb[1][1], Cnb[1][2], Cnb[1][3],
                         afr[cc][1][0], afr[cc][1][1], afr[cc][1][2], afr[cc][1][3], b0, b1);
            }
        }

        // prefetch stage t+8 (into the stage consumed at iter t-1)
        {
            const int tp = t + RING;
            #pragma unroll
            for (int s = 0; s < 3; s++) {
                cp16_pred(sbase + (unsigned int)(((tp & (RING - 1)) * STAGE_B)) + sdst[s],
                          xsrc[s] + (size_t)min(tp, plastS[s]) * 44,
                          pval[s] && (tp <= plastS[s]));
            }
            CP_COMMIT();
        }

        // merge (off critical path)
        #pragma unroll
        for (int j = 0; j < 2; j++)
            #pragma unroll
            for (int q = 0; q < 4; q++) Cc[j][q] = Cna[j][q] + Cnb[j][q];
    }
}

// ─────────────────────────────────────────────────────────────────────────────
// Finalize: per-path fc dot -> smem; counts + block scan -> segment sums;
// shfl softmax. One 1024-thread block.
// ─────────────────────────────────────────────────────────────────────────────
__global__ void __launch_bounds__(NGROUPS)
finalize_kernel(const int* __restrict__ group_ids,
                const float* __restrict__ fc_W,
                const float* __restrict__ fc_b,
                float* __restrict__ out)
{
    __shared__ float sdot[NPATHS];
    __shared__ int   scnt[NGROUPS];
    __shared__ int   sstart[NGROUPS];
    __shared__ int   wsum[32];
    __shared__ float warpred[32];
    __shared__ float bc;

    const int tid = threadIdx.x;
    const int wid = tid >> 5;
    const int lid = tid & 31;

    float w[8];
    #pragma unroll
    for (int j = 0; j < 8; j++) w[j] = fc_W[j];

    scnt[tid] = 0;
    __syncthreads();

    #pragma unroll
    for (int r = 0; r < NPATHS / NGROUPS; r++) {
        const int i = tid + r * NGROUPS;
        const float4* hp = (const float4*)(g_hlast + i * H_DIM);
        float4 h0 = hp[0], h1 = hp[1];
        float s = h0.x * w[0];
        s = fmaf(h0.y, w[1], s);
        s = fmaf(h0.z, w[2], s);
        s = fmaf(h0.w, w[3], s);
        s = fmaf(h1.x, w[4], s);
        s = fmaf(h1.y, w[5], s);
        s = fmaf(h1.z, w[6], s);
        s = fmaf(h1.w, w[7], s);
        sdot[i] = s;
        atomicAdd(&scnt[group_ids[i]], 1);
    }
    __syncthreads();

    const int myc = scnt[tid];
    int inc = myc;
    #pragma unroll
    for (int d = 1; d < 32; d <<= 1) {
        int n = __shfl_up_sync(0xffffffffu, inc, d);
        if (lid >= d) inc += n;
    }
    if (lid == 31) wsum[wid] = inc;
    __syncthreads();
    if (wid == 0) {
        int v = wsum[lid];
        int iv = v;
        #pragma unroll
        for (int d = 1; d < 32; d <<= 1) {
            int n = __shfl_up_sync(0xffffffffu, iv, d);
            if (lid >= d) iv += n;
        }
        wsum[lid] = iv - v;
    }
    __syncthreads();
    sstart[tid] = inc - myc + wsum[wid];
    __syncthreads();

    float logit = fc_b[0];
    {
        const int s = sstart[tid];
        const int e = s + myc;
        for (int i = s; i < e; i++) logit += sdot[i];
    }

    float m = logit;
    #pragma unroll
    for (int off = 16; off > 0; off >>= 1) m = fmaxf(m, __shfl_xor_sync(0xffffffffu, m, off));
    if (lid == 0) warpred[wid] = m;
    __syncthreads();
    if (wid == 0) {
        float v = warpred[lid];
        #pragma unroll
        for (int off = 16; off > 0; off >>= 1) v = fmaxf(v, __shfl_xor_sync(0xffffffffu, v, off));
        if (lid == 0) bc = v;
    }
    __syncthreads();
    const float mx = bc;

    const float e = __expf(logit - mx);

    float s = e;
    #pragma unroll
    for (int off = 16; off > 0; off >>= 1) s += __shfl_xor_sync(0xffffffffu, s, off);
    __syncthreads();
    if (lid == 0) warpred[wid] = s;
    __syncthreads();
    if (wid == 0) {
        float v = warpred[lid];
        #pragma unroll
        for (int off = 16; off > 0; off >>= 1) v += __shfl_xor_sync(0xffffffffu, v, off);
        if (lid == 0) bc = v;
    }
    __syncthreads();

    out[tid] = e * fast_rcp(bc);
}

extern "C" void kernel_launch(void* const* d_in, const int* in_sizes, int n_in,
                              void* d_out, int out_size)
{
    const float* x      = (const float*)d_in[0];
    const float* W_ih   = (const float*)d_in[1];
    const float* W_hh   = (const float*)d_in[2];
    const float* b_ih   = (const float*)d_in[3];
    const float* b_hh   = (const float*)d_in[4];
    const float* fc_W   = (const float*)d_in[5];
    const float* fc_b   = (const float*)d_in[6];
    const int*   last_i = (const int*)d_in[7];
    const int*   gids   = (const int*)d_in[8];
    float*       out    = (float*)d_out;

    sort_kernel<<<1, 1024>>>(last_i);
    lstm_kernel<<<NBLK, 32>>>(x, W_ih, W_hh, b_ih, b_hh, last_i);
    finalize_kernel<<<1, NGROUPS>>>(gids, fc_W, fc_b, out);
}